// round 3
// baseline (speedup 1.0000x reference)
#include <cuda_runtime.h>
#include <math_constants.h>
#include <cstddef>

#define DIMC   512
#define HD     64
#define NHEADS 8
#define BATCH  4
#define SEQN   2048
#define SEQM   2048
#define ATT_SCALE 0.125f   // 64^-0.5

// ---------------- scratch (device globals: allocation-free) ----------------
__device__ float g_Q [BATCH * SEQN * DIMC];        // 16 MB
__device__ float g_KV[BATCH * SEQM * 2 * DIMC];    // 32 MB
__device__ float g_O [BATCH * SEQN * DIMC];        // 16 MB

// ---------------------------------------------------------------------------
// SGEMM: C[M,N] = A[M,K] @ B[K,N], row-major. Requires M%128==0, N%128==0, K%8==0.
// 128x128 block tile, K-tile 8, 256 threads, 8x8 per thread.
// ---------------------------------------------------------------------------
__global__ __launch_bounds__(256) void sgemm128(const float* __restrict__ A,
                                                const float* __restrict__ B,
                                                float* __restrict__ C,
                                                int M, int N, int K)
{
    __shared__ __align__(16) float As[8][128];
    __shared__ __align__(16) float Bs[8][128];

    const int tid = threadIdx.x;
    const int tx  = tid & 15;       // 0..15  -> 8 output cols
    const int ty  = tid >> 4;       // 0..15  -> 8 output rows
    const int bm0 = blockIdx.y * 128;
    const int bn0 = blockIdx.x * 128;

    // A tile loader: 128 rows x 8 cols; one float4 per thread
    const int arow = tid >> 1;            // 0..127
    const int acol = (tid & 1) * 4;       // 0 or 4
    // B tile loader: 8 rows x 128 cols; one float4 per thread
    const int brow = tid >> 5;            // 0..7
    const int bcol = (tid & 31) * 4;      // 0..124

    const float* Aptr = A + (size_t)(bm0 + arow) * K + acol;
    const float* Bptr = B + (size_t)brow * N + bn0 + bcol;

    float acc[8][8];
#pragma unroll
    for (int i = 0; i < 8; i++)
#pragma unroll
        for (int j = 0; j < 8; j++) acc[i][j] = 0.0f;

    for (int k0 = 0; k0 < K; k0 += 8) {
        float4 av = *(const float4*)(Aptr + k0);
        float4 bv = *(const float4*)(Bptr + (size_t)k0 * N);
        __syncthreads();   // previous tile's compute finished
        As[acol + 0][arow] = av.x;
        As[acol + 1][arow] = av.y;
        As[acol + 2][arow] = av.z;
        As[acol + 3][arow] = av.w;
        *(float4*)&Bs[brow][bcol] = bv;
        __syncthreads();
#pragma unroll
        for (int kk = 0; kk < 8; kk++) {
            float4 a0 = *(const float4*)&As[kk][ty * 8];
            float4 a1 = *(const float4*)&As[kk][ty * 8 + 4];
            float4 b0 = *(const float4*)&Bs[kk][tx * 8];
            float4 b1 = *(const float4*)&Bs[kk][tx * 8 + 4];
            float a[8] = {a0.x, a0.y, a0.z, a0.w, a1.x, a1.y, a1.z, a1.w};
            float b[8] = {b0.x, b0.y, b0.z, b0.w, b1.x, b1.y, b1.z, b1.w};
#pragma unroll
            for (int i = 0; i < 8; i++)
#pragma unroll
                for (int j = 0; j < 8; j++)
                    acc[i][j] = fmaf(a[i], b[j], acc[i][j]);
        }
    }

#pragma unroll
    for (int i = 0; i < 8; i++) {
        float* crow = C + (size_t)(bm0 + ty * 8 + i) * N + bn0 + tx * 8;
        float4 c0 = {acc[i][0], acc[i][1], acc[i][2], acc[i][3]};
        float4 c1 = {acc[i][4], acc[i][5], acc[i][6], acc[i][7]};
        *(float4*)(crow)     = c0;
        *(float4*)(crow + 4) = c1;
    }
}

// ---------------------------------------------------------------------------
// Flash-style attention.
// Grid: (N/64, NHEADS, BATCH), 256 threads.
// Each CTA: 64 queries of one (b,h); iterates M in 64-wide tiles with online
// softmax. Q/K stored [d][i] with rotation swizzle (i+d)&63 for conflict-free
// transposed stores + tiled reads. P reuses the K buffer.
// Mask is read as int32 (bool widened by the harness); nonzero = visible.
// ---------------------------------------------------------------------------
__global__ __launch_bounds__(256) void attn_kernel(const float* __restrict__ Qm,
                                                   const float* __restrict__ KVm,
                                                   const int* __restrict__ mask,
                                                   float* __restrict__ Om)
{
    __shared__ __align__(16) float Qts[64][64];  // [d][(i+d)&63]
    __shared__ __align__(16) float KPs[64][64];  // K: [d][(j+d)&63]; later P: [j][(i+j)&63]
    __shared__ __align__(16) float Vs [64][64];  // [j][d]

    const int tid = threadIdx.x;
    const int tx  = tid & 15;     // 4 cols (j or d)
    const int ty  = tid >> 4;     // 4 rows (i)
    const int n0  = blockIdx.x * 64;
    const int h   = blockIdx.y;
    const int b   = blockIdx.z;

    const float* Qbase  = Qm  + ((size_t)b * SEQN) * DIMC       + h * HD;
    const float* KVbase = KVm + ((size_t)b * SEQM) * (2 * DIMC) + h * HD;
    const int* mrow = mask + ((size_t)b * SEQN + n0) * SEQM;

    // ---- load Q tile (transposed + swizzled) ----
#pragma unroll
    for (int e = 0; e < 16; e++) {
        int idx = tid + e * 256;          // 0..4095
        int i = idx >> 6, d = idx & 63;   // coalesced over d
        Qts[d][(i + d) & 63] = Qbase[(size_t)(n0 + i) * DIMC + d];
    }

    float acc[4][4];
#pragma unroll
    for (int r = 0; r < 4; r++)
#pragma unroll
        for (int c = 0; c < 4; c++) acc[r][c] = 0.0f;
    float mmax[4], lsum[4];
#pragma unroll
    for (int r = 0; r < 4; r++) { mmax[r] = -CUDART_INF_F; lsum[r] = 0.0f; }

    __syncthreads();

    for (int t = 0; t < SEQM / 64; t++) {
        const int m0 = t * 64;
        // ---- load K (transposed+swizzled) and V tiles ----
#pragma unroll
        for (int e = 0; e < 16; e++) {
            int idx = tid + e * 256;
            int j = idx >> 6, d = idx & 63;
            const float* kvrow = KVbase + (size_t)(m0 + j) * (2 * DIMC);
            KPs[d][(j + d) & 63] = kvrow[d];          // K
            Vs[j][d]             = kvrow[DIMC + d];   // V
        }
        __syncthreads();

        // ---- S = Q K^T ----
        float s[4][4];
#pragma unroll
        for (int r = 0; r < 4; r++)
#pragma unroll
            for (int c = 0; c < 4; c++) s[r][c] = 0.0f;
#pragma unroll 8
        for (int d = 0; d < 64; d++) {
            float q[4], k[4];
#pragma unroll
            for (int r = 0; r < 4; r++) q[r] = Qts[d][(ty * 4 + r + d) & 63];
#pragma unroll
            for (int c = 0; c < 4; c++) k[c] = KPs[d][(tx * 4 + c + d) & 63];
#pragma unroll
            for (int r = 0; r < 4; r++)
#pragma unroll
                for (int c = 0; c < 4; c++) s[r][c] = fmaf(q[r], k[c], s[r][c]);
        }
        __syncthreads();   // all K reads done before P overwrites KPs

        // ---- scale + mask ----
#pragma unroll
        for (int r = 0; r < 4; r++) {
            const int* mr = mrow + (size_t)(ty * 4 + r) * SEQM + m0 + tx * 4;
#pragma unroll
            for (int c = 0; c < 4; c++) {
                s[r][c] *= ATT_SCALE;
                if (mr[c] == 0) s[r][c] = -CUDART_INF_F;
            }
        }

        // ---- online softmax (row groups of 16 lanes share rows) ----
        float alpha[4];
#pragma unroll
        for (int r = 0; r < 4; r++) {
            float tm = fmaxf(fmaxf(s[r][0], s[r][1]), fmaxf(s[r][2], s[r][3]));
#pragma unroll
            for (int o = 8; o >= 1; o >>= 1)
                tm = fmaxf(tm, __shfl_xor_sync(0xffffffffu, tm, o));
            float mnew = fmaxf(mmax[r], tm);
            float ssum = 0.0f;
#pragma unroll
            for (int c = 0; c < 4; c++) {
                float p = (s[r][c] == -CUDART_INF_F) ? 0.0f : __expf(s[r][c] - mnew);
                s[r][c] = p;
                ssum += p;
            }
#pragma unroll
            for (int o = 8; o >= 1; o >>= 1)
                ssum += __shfl_xor_sync(0xffffffffu, ssum, o);
            alpha[r] = (mmax[r] == -CUDART_INF_F) ? 0.0f : __expf(mmax[r] - mnew);
            lsum[r] = lsum[r] * alpha[r] + ssum;
            mmax[r] = mnew;
        }
#pragma unroll
        for (int r = 0; r < 4; r++)
#pragma unroll
            for (int c = 0; c < 4; c++) acc[r][c] *= alpha[r];

        // ---- stage P into KPs as [j][(i+j)&63] ----
#pragma unroll
        for (int r = 0; r < 4; r++)
#pragma unroll
            for (int c = 0; c < 4; c++) {
                int i = ty * 4 + r, j = tx * 4 + c;
                KPs[j][(i + j) & 63] = s[r][c];
            }
        __syncthreads();

        // ---- acc += P @ V ----
#pragma unroll 8
        for (int j = 0; j < 64; j++) {
            float p[4];
#pragma unroll
            for (int r = 0; r < 4; r++) p[r] = KPs[j][(ty * 4 + r + j) & 63];
            float4 v = *(const float4*)&Vs[j][tx * 4];
            float vv[4] = {v.x, v.y, v.z, v.w};
#pragma unroll
            for (int r = 0; r < 4; r++)
#pragma unroll
                for (int c = 0; c < 4; c++) acc[r][c] = fmaf(p[r], vv[c], acc[r][c]);
        }
        __syncthreads();   // before next tile's loads overwrite KPs/Vs
    }

    // ---- normalize + write O ----
#pragma unroll
    for (int r = 0; r < 4; r++) {
        float inv = 1.0f / lsum[r];
        int i = ty * 4 + r;
        float4 o = {acc[r][0] * inv, acc[r][1] * inv, acc[r][2] * inv, acc[r][3] * inv};
        *(float4*)&Om[(size_t)(b * SEQN + n0 + i) * DIMC + h * HD + tx * 4] = o;
    }
}

// ---------------------------------------------------------------------------
extern "C" void kernel_launch(void* const* d_in, const int* in_sizes, int n_in,
                              void* d_out, int out_size)
{
    const float* x    = (const float*)d_in[0];
    const float* ctx  = (const float*)d_in[1];
    const int*   mask = (const int*)d_in[2];
    const float* Wq   = (const float*)d_in[3];
    const float* Wkv  = (const float*)d_in[4];
    const float* Wo   = (const float*)d_in[5];
    float*       out  = (float*)d_out;

    float *gQ, *gKV, *gO;
    cudaGetSymbolAddress((void**)&gQ,  g_Q);
    cudaGetSymbolAddress((void**)&gKV, g_KV);
    cudaGetSymbolAddress((void**)&gO,  g_O);

    const int Mrows = BATCH * SEQN;   // 8192

    // Q = x @ Wq   (8192 x 512 x 512)
    sgemm128<<<dim3(DIMC / 128, Mrows / 128), 256>>>(x, Wq, gQ, Mrows, DIMC, DIMC);
    // KV = context @ Wkv  (8192 x 1024 x 512)
    sgemm128<<<dim3(2 * DIMC / 128, Mrows / 128), 256>>>(ctx, Wkv, gKV, Mrows, 2 * DIMC, DIMC);
    // attention -> gO
    attn_kernel<<<dim3(SEQN / 64, NHEADS, BATCH), 256>>>(gQ, gKV, mask, gO);
    // out = gO @ Wo  (8192 x 512 x 512)
    sgemm128<<<dim3(DIMC / 128, Mrows / 128), 256>>>(gO, Wo, out, Mrows, DIMC, DIMC);
}

// round 4
// speedup vs baseline: 1.8619x; 1.8619x over previous
#include <cuda_runtime.h>
#include <math_constants.h>
#include <cstddef>

#define DIMC   512
#define HD     64
#define NHEADS 8
#define BATCH  4
#define SEQN   2048
#define SEQM   2048
#define ATT_SCALE 0.125f   // 64^-0.5

#define KS_LD 68   // K smem leading stride (=4 mod 32 -> conflict-free B-frag reads)
#define VS_LD 72   // V smem leading stride (=8 mod 32)

// ---------------- scratch (device globals: allocation-free) ----------------
__device__ float g_Q [BATCH * SEQN * DIMC];        // 16 MB
__device__ float g_KV[BATCH * SEQM * 2 * DIMC];    // 32 MB
__device__ float g_O [BATCH * SEQN * DIMC];        // 16 MB

// ---------------------------------------------------------------------------
// fp32 SGEMM (unchanged, known-good): C[M,N] = A[M,K] @ B[K,N]
// ---------------------------------------------------------------------------
__global__ __launch_bounds__(256) void sgemm128(const float* __restrict__ A,
                                                const float* __restrict__ B,
                                                float* __restrict__ C,
                                                int M, int N, int K)
{
    __shared__ __align__(16) float As[8][128];
    __shared__ __align__(16) float Bs[8][128];

    const int tid = threadIdx.x;
    const int tx  = tid & 15;
    const int ty  = tid >> 4;
    const int bm0 = blockIdx.y * 128;
    const int bn0 = blockIdx.x * 128;

    const int arow = tid >> 1;
    const int acol = (tid & 1) * 4;
    const int brow = tid >> 5;
    const int bcol = (tid & 31) * 4;

    const float* Aptr = A + (size_t)(bm0 + arow) * K + acol;
    const float* Bptr = B + (size_t)brow * N + bn0 + bcol;

    float acc[8][8];
#pragma unroll
    for (int i = 0; i < 8; i++)
#pragma unroll
        for (int j = 0; j < 8; j++) acc[i][j] = 0.0f;

    for (int k0 = 0; k0 < K; k0 += 8) {
        float4 av = *(const float4*)(Aptr + k0);
        float4 bv = *(const float4*)(Bptr + (size_t)k0 * N);
        __syncthreads();
        As[acol + 0][arow] = av.x;
        As[acol + 1][arow] = av.y;
        As[acol + 2][arow] = av.z;
        As[acol + 3][arow] = av.w;
        *(float4*)&Bs[brow][bcol] = bv;
        __syncthreads();
#pragma unroll
        for (int kk = 0; kk < 8; kk++) {
            float4 a0 = *(const float4*)&As[kk][ty * 8];
            float4 a1 = *(const float4*)&As[kk][ty * 8 + 4];
            float4 b0 = *(const float4*)&Bs[kk][tx * 8];
            float4 b1 = *(const float4*)&Bs[kk][tx * 8 + 4];
            float a[8] = {a0.x, a0.y, a0.z, a0.w, a1.x, a1.y, a1.z, a1.w};
            float b[8] = {b0.x, b0.y, b0.z, b0.w, b1.x, b1.y, b1.z, b1.w};
#pragma unroll
            for (int i = 0; i < 8; i++)
#pragma unroll
                for (int j = 0; j < 8; j++)
                    acc[i][j] = fmaf(a[i], b[j], acc[i][j]);
        }
    }

#pragma unroll
    for (int i = 0; i < 8; i++) {
        float* crow = C + (size_t)(bm0 + ty * 8 + i) * N + bn0 + tx * 8;
        float4 c0 = {acc[i][0], acc[i][1], acc[i][2], acc[i][3]};
        float4 c1 = {acc[i][4], acc[i][5], acc[i][6], acc[i][7]};
        *(float4*)(crow)     = c0;
        *(float4*)(crow + 4) = c1;
    }
}

// ---------------------------------------------------------------------------
// tf32 helpers
// ---------------------------------------------------------------------------
__device__ __forceinline__ float to_tf32(float x) {
    unsigned u;
    asm("cvt.rna.tf32.f32 %0, %1;" : "=r"(u) : "f"(x));
    return __uint_as_float(u);
}
__device__ __forceinline__ unsigned tf32_bits(float x) {
    unsigned u;
    asm("cvt.rna.tf32.f32 %0, %1;" : "=r"(u) : "f"(x));
    return u;
}

__device__ __forceinline__ void mma_tf32(float c[4], const unsigned a[4],
                                         unsigned b0, unsigned b1)
{
    asm volatile(
        "mma.sync.aligned.m16n8k8.row.col.f32.tf32.tf32.f32 "
        "{%0,%1,%2,%3},{%4,%5,%6,%7},{%8,%9},{%0,%1,%2,%3};"
        : "+f"(c[0]), "+f"(c[1]), "+f"(c[2]), "+f"(c[3])
        : "r"(a[0]), "r"(a[1]), "r"(a[2]), "r"(a[3]), "r"(b0), "r"(b1));
}

// ---------------------------------------------------------------------------
// Tensor-core flash attention (tf32 mma.sync).
// Grid: (SEQN/64, NHEADS, BATCH), 128 threads (4 warps).
// Warp w owns query rows [16w, 16w+16). Q as A-fragments in registers.
// K/V staged in smem (tf32-rounded), padded strides for conflict-free frags.
// P converted C-frag -> A-frag via register shuffles (no smem round trip).
// ---------------------------------------------------------------------------
__global__ __launch_bounds__(128) void attn_tc(const float* __restrict__ Qm,
                                               const float* __restrict__ KVm,
                                               const int* __restrict__ mask,
                                               float* __restrict__ Om)
{
    __shared__ __align__(16) float Ks[64 * KS_LD];   // also Q staging
    __shared__ __align__(16) float Vs[64 * VS_LD];

    const int tid  = threadIdx.x;
    const int warp = tid >> 5;
    const int lane = tid & 31;
    const int q4   = lane >> 2;       // 0..7 (row group / n index)
    const int l4   = lane & 3;        // 0..3 (col group / k index)
    const int n0   = blockIdx.x * 64;
    const int h    = blockIdx.y;
    const int b    = blockIdx.z;
    const int r0   = warp * 16;       // warp's first query row in the tile

    const float* Qbase  = Qm  + ((size_t)b * SEQN) * DIMC       + h * HD;
    const float* KVbase = KVm + ((size_t)b * SEQM) * (2 * DIMC) + h * HD;

    // ---- stage Q tile (64x64, tf32-rounded) in Ks ----
#pragma unroll
    for (int e = 0; e < 8; e++) {
        int i4 = tid + e * 128;            // 0..1023 float4s
        int i  = i4 >> 4;                  // row 0..63
        int d4 = (i4 & 15) << 2;           // 0,4,...,60
        float4 v = *(const float4*)(Qbase + (size_t)(n0 + i) * DIMC + d4);
        float* dst = &Ks[i * KS_LD + d4];
        dst[0] = to_tf32(v.x); dst[1] = to_tf32(v.y);
        dst[2] = to_tf32(v.z); dst[3] = to_tf32(v.w);
    }
    __syncthreads();

    // ---- build Q A-fragments: qa[kt] covers d = 8kt..8kt+7 ----
    unsigned qa[8][4];
#pragma unroll
    for (int kt = 0; kt < 8; kt++) {
        int r = r0 + q4;
        qa[kt][0] = __float_as_uint(Ks[(r    ) * KS_LD + kt * 8 + l4    ]);
        qa[kt][1] = __float_as_uint(Ks[(r + 8) * KS_LD + kt * 8 + l4    ]);
        qa[kt][2] = __float_as_uint(Ks[(r    ) * KS_LD + kt * 8 + l4 + 4]);
        qa[kt][3] = __float_as_uint(Ks[(r + 8) * KS_LD + kt * 8 + l4 + 4]);
    }
    __syncthreads();   // Ks reusable for K tiles

    // ---- running softmax state (two rows per thread: lo=q4, hi=q4+8) ----
    float oc[8][4];
#pragma unroll
    for (int nt = 0; nt < 8; nt++)
#pragma unroll
        for (int c = 0; c < 4; c++) oc[nt][c] = 0.0f;
    float mrun_lo = -CUDART_INF_F, mrun_hi = -CUDART_INF_F;
    float lsum_lo = 0.0f, lsum_hi = 0.0f;

    const int i0 = n0 + r0 + q4;       // global query row (lo)
    const int i1 = i0 + 8;             // (hi)
    const int* mrow0 = mask + ((size_t)b * SEQN + i0) * SEQM;
    const int* mrow1 = mask + ((size_t)b * SEQN + i1) * SEQM;

    for (int t = 0; t < SEQM / 64; t++) {
        const int m0 = t * 64;

        // ---- load K,V tile (tf32-rounded) ----
#pragma unroll
        for (int e = 0; e < 8; e++) {
            int i4 = tid + e * 128;
            int j  = i4 >> 4;
            int d4 = (i4 & 15) << 2;
            const float* row = KVbase + (size_t)(m0 + j) * (2 * DIMC);
            float4 kv = *(const float4*)(row + d4);
            float4 vv = *(const float4*)(row + DIMC + d4);
            float* kd = &Ks[j * KS_LD + d4];
            float* vd = &Vs[j * VS_LD + d4];
            kd[0] = to_tf32(kv.x); kd[1] = to_tf32(kv.y);
            kd[2] = to_tf32(kv.z); kd[3] = to_tf32(kv.w);
            vd[0] = to_tf32(vv.x); vd[1] = to_tf32(vv.y);
            vd[2] = to_tf32(vv.z); vd[3] = to_tf32(vv.w);
        }
        __syncthreads();

        // ---- S = Q K^T  (sc[nt]: keys j = m0 + 8nt .. +7) ----
        float sc[8][4];
#pragma unroll
        for (int nt = 0; nt < 8; nt++)
#pragma unroll
            for (int c = 0; c < 4; c++) sc[nt][c] = 0.0f;
#pragma unroll
        for (int kt = 0; kt < 8; kt++) {
#pragma unroll
            for (int nt = 0; nt < 8; nt++) {
                int jrow = nt * 8 + q4;
                unsigned b0 = __float_as_uint(Ks[jrow * KS_LD + kt * 8 + l4    ]);
                unsigned b1 = __float_as_uint(Ks[jrow * KS_LD + kt * 8 + l4 + 4]);
                mma_tf32(sc[nt], qa[kt], b0, b1);
            }
        }

        // ---- scale + mask ----
#pragma unroll
        for (int nt = 0; nt < 8; nt++) {
            int j = m0 + nt * 8 + 2 * l4;
            int2 ml = *(const int2*)(mrow0 + j);
            int2 mh = *(const int2*)(mrow1 + j);
            sc[nt][0] = ml.x ? sc[nt][0] * ATT_SCALE : -CUDART_INF_F;
            sc[nt][1] = ml.y ? sc[nt][1] * ATT_SCALE : -CUDART_INF_F;
            sc[nt][2] = mh.x ? sc[nt][2] * ATT_SCALE : -CUDART_INF_F;
            sc[nt][3] = mh.y ? sc[nt][3] * ATT_SCALE : -CUDART_INF_F;
        }

        // ---- online softmax (rows shared by lanes with equal lane>>2) ----
        float tml = -CUDART_INF_F, tmh = -CUDART_INF_F;
#pragma unroll
        for (int nt = 0; nt < 8; nt++) {
            tml = fmaxf(tml, fmaxf(sc[nt][0], sc[nt][1]));
            tmh = fmaxf(tmh, fmaxf(sc[nt][2], sc[nt][3]));
        }
        tml = fmaxf(tml, __shfl_xor_sync(0xffffffffu, tml, 1));
        tml = fmaxf(tml, __shfl_xor_sync(0xffffffffu, tml, 2));
        tmh = fmaxf(tmh, __shfl_xor_sync(0xffffffffu, tmh, 1));
        tmh = fmaxf(tmh, __shfl_xor_sync(0xffffffffu, tmh, 2));

        float mnew_lo = fmaxf(mrun_lo, tml);
        float mnew_hi = fmaxf(mrun_hi, tmh);
        bool  inf_lo  = (mnew_lo == -CUDART_INF_F);
        bool  inf_hi  = (mnew_hi == -CUDART_INF_F);

        float ssl = 0.0f, ssh = 0.0f;
#pragma unroll
        for (int nt = 0; nt < 8; nt++) {
            float p0 = inf_lo ? 0.0f : __expf(sc[nt][0] - mnew_lo);
            float p1 = inf_lo ? 0.0f : __expf(sc[nt][1] - mnew_lo);
            float p2 = inf_hi ? 0.0f : __expf(sc[nt][2] - mnew_hi);
            float p3 = inf_hi ? 0.0f : __expf(sc[nt][3] - mnew_hi);
            sc[nt][0] = p0; sc[nt][1] = p1; sc[nt][2] = p2; sc[nt][3] = p3;
            ssl += p0 + p1;
            ssh += p2 + p3;
        }
        ssl += __shfl_xor_sync(0xffffffffu, ssl, 1);
        ssl += __shfl_xor_sync(0xffffffffu, ssl, 2);
        ssh += __shfl_xor_sync(0xffffffffu, ssh, 1);
        ssh += __shfl_xor_sync(0xffffffffu, ssh, 2);

        float alpha_lo = (mrun_lo == -CUDART_INF_F) ? 0.0f : __expf(mrun_lo - mnew_lo);
        float alpha_hi = (mrun_hi == -CUDART_INF_F) ? 0.0f : __expf(mrun_hi - mnew_hi);
        lsum_lo = lsum_lo * alpha_lo + ssl;
        lsum_hi = lsum_hi * alpha_hi + ssh;
        mrun_lo = mnew_lo;
        mrun_hi = mnew_hi;
#pragma unroll
        for (int nt = 0; nt < 8; nt++) {
            oc[nt][0] *= alpha_lo; oc[nt][1] *= alpha_lo;
            oc[nt][2] *= alpha_hi; oc[nt][3] *= alpha_hi;
        }

        // ---- O += P @ V ; P C-frag -> A-frag via shuffles ----
        const int base = lane & ~3;
        const int src  = base | (l4 >> 1);
        const int src2 = src + 2;
        const bool odd = lane & 1;
#pragma unroll
        for (int kt = 0; kt < 8; kt++) {
            float c0 = sc[kt][0], c1 = sc[kt][1], c2 = sc[kt][2], c3 = sc[kt][3];
            float t00 = __shfl_sync(0xffffffffu, c0, src);
            float t01 = __shfl_sync(0xffffffffu, c1, src);
            float t10 = __shfl_sync(0xffffffffu, c2, src);
            float t11 = __shfl_sync(0xffffffffu, c3, src);
            float t20 = __shfl_sync(0xffffffffu, c0, src2);
            float t21 = __shfl_sync(0xffffffffu, c1, src2);
            float t30 = __shfl_sync(0xffffffffu, c2, src2);
            float t31 = __shfl_sync(0xffffffffu, c3, src2);
            unsigned pa[4];
            pa[0] = tf32_bits(odd ? t01 : t00);
            pa[1] = tf32_bits(odd ? t11 : t10);
            pa[2] = tf32_bits(odd ? t21 : t20);
            pa[3] = tf32_bits(odd ? t31 : t30);
#pragma unroll
            for (int nt = 0; nt < 8; nt++) {
                int vrow = kt * 8 + l4;
                unsigned b0 = __float_as_uint(Vs[(vrow    ) * VS_LD + nt * 8 + q4]);
                unsigned b1 = __float_as_uint(Vs[(vrow + 4) * VS_LD + nt * 8 + q4]);
                mma_tf32(oc[nt], pa, b0, b1);
            }
        }
        __syncthreads();   // PV reads done before next tile's stores
    }

    // ---- normalize + write O ----
    float inv_lo = 1.0f / lsum_lo;
    float inv_hi = 1.0f / lsum_hi;
    float* orow0 = Om + (size_t)(b * SEQN + i0) * DIMC + h * HD;
    float* orow1 = Om + (size_t)(b * SEQN + i1) * DIMC + h * HD;
#pragma unroll
    for (int nt = 0; nt < 8; nt++) {
        int d0 = nt * 8 + 2 * l4;
        float2 lo = {oc[nt][0] * inv_lo, oc[nt][1] * inv_lo};
        float2 hi = {oc[nt][2] * inv_hi, oc[nt][3] * inv_hi};
        *(float2*)(orow0 + d0) = lo;
        *(float2*)(orow1 + d0) = hi;
    }
}

// ---------------------------------------------------------------------------
extern "C" void kernel_launch(void* const* d_in, const int* in_sizes, int n_in,
                              void* d_out, int out_size)
{
    const float* x    = (const float*)d_in[0];
    const float* ctx  = (const float*)d_in[1];
    const int*   mask = (const int*)d_in[2];
    const float* Wq   = (const float*)d_in[3];
    const float* Wkv  = (const float*)d_in[4];
    const float* Wo   = (const float*)d_in[5];
    float*       out  = (float*)d_out;

    float *gQ, *gKV, *gO;
    cudaGetSymbolAddress((void**)&gQ,  g_Q);
    cudaGetSymbolAddress((void**)&gKV, g_KV);
    cudaGetSymbolAddress((void**)&gO,  g_O);

    const int Mrows = BATCH * SEQN;   // 8192

    sgemm128<<<dim3(DIMC / 128, Mrows / 128), 256>>>(x, Wq, gQ, Mrows, DIMC, DIMC);
    sgemm128<<<dim3(2 * DIMC / 128, Mrows / 128), 256>>>(ctx, Wkv, gKV, Mrows, 2 * DIMC, DIMC);
    attn_tc<<<dim3(SEQN / 64, NHEADS, BATCH), 128>>>(gQ, gKV, mask, gO);
    sgemm128<<<dim3(DIMC / 128, Mrows / 128), 256>>>(gO, Wo, out, Mrows, DIMC, DIMC);
}

// round 5
// speedup vs baseline: 2.6575x; 1.4273x over previous
#include <cuda_runtime.h>
#include <math_constants.h>
#include <cstddef>

#define DIMC   512
#define HD     64
#define NHEADS 8
#define BATCH  4
#define SEQN   2048
#define SEQM   2048
#define ATT_SCALE 0.125f   // 64^-0.5

#define KS_LD 68   // attention K smem stride
#define VS_LD 72   // attention V smem stride

#define GA_LD 36   // gemm A smem stride (128 rows x 32 cols)
#define GB_LD 136  // gemm B smem stride (32 rows x 128 cols)

// ---------------- scratch (device globals: allocation-free) ----------------
__device__ float g_Q [BATCH * SEQN * DIMC];        // 16 MB
__device__ float g_KV[BATCH * SEQM * 2 * DIMC];    // 32 MB
__device__ float g_O [BATCH * SEQN * DIMC];        // 16 MB

// ---------------------------------------------------------------------------
// tf32 helpers
// ---------------------------------------------------------------------------
__device__ __forceinline__ float to_tf32(float x) {
    unsigned u;
    asm("cvt.rna.tf32.f32 %0, %1;" : "=r"(u) : "f"(x));
    return __uint_as_float(u);
}
__device__ __forceinline__ unsigned tf32_bits(float x) {
    unsigned u;
    asm("cvt.rna.tf32.f32 %0, %1;" : "=r"(u) : "f"(x));
    return u;
}
__device__ __forceinline__ void mma_tf32(float c[4], const unsigned a[4],
                                         unsigned b0, unsigned b1)
{
    asm volatile(
        "mma.sync.aligned.m16n8k8.row.col.f32.tf32.tf32.f32 "
        "{%0,%1,%2,%3},{%4,%5,%6,%7},{%8,%9},{%0,%1,%2,%3};"
        : "+f"(c[0]), "+f"(c[1]), "+f"(c[2]), "+f"(c[3])
        : "r"(a[0]), "r"(a[1]), "r"(a[2]), "r"(a[3]), "r"(b0), "r"(b1));
}

// ---------------------------------------------------------------------------
// tf32 tensor-core GEMM: C[M,N] = A[M,K] @ B[K,N], row-major.
// CTA tile 128x128, K-tile 32, 256 threads = 8 warps (4M x 2N), warp 32x64.
// Register-prefetch double buffering; cvt.rna at smem store.
// Requires M%128==0, N%128==0, K%32==0.
// ---------------------------------------------------------------------------
__global__ __launch_bounds__(256) void tgemm128(const float* __restrict__ A,
                                                const float* __restrict__ B,
                                                float* __restrict__ C,
                                                int M, int N, int K)
{
    __shared__ __align__(16) float As[128 * GA_LD];
    __shared__ __align__(16) float Bs[32 * GB_LD];

    const int tid  = threadIdx.x;
    const int warp = tid >> 5;
    const int lane = tid & 31;
    const int q4   = lane >> 2;    // 0..7
    const int l4   = lane & 3;     // 0..3
    const int wm   = (warp >> 1) * 32;   // warp M offset in tile
    const int wn   = (warp & 1) * 64;    // warp N offset in tile
    const int bm0  = blockIdx.y * 128;
    const int bn0  = blockIdx.x * 128;

    // A loader: f4 idx = tid + e*256; row = idx>>3, col4 = (idx&7)*4
    const int a_row  = tid >> 3;          // base row for e=0 (rows advance by 32 per e)
    const int a_col4 = (tid & 7) * 4;
    // B loader: row = idx>>5, col4 = (idx&31)*4 (rows advance by 8 per e)
    const int b_row  = tid >> 5;
    const int b_col4 = (tid & 31) * 4;

    const float* Abase = A + (size_t)(bm0 + a_row) * K + a_col4;
    const float* Bbase = B + (size_t)b_row * N + bn0 + b_col4;

    float acc[2][8][4];
#pragma unroll
    for (int mf = 0; mf < 2; mf++)
#pragma unroll
        for (int nf = 0; nf < 8; nf++)
#pragma unroll
            for (int c = 0; c < 4; c++) acc[mf][nf][c] = 0.0f;

    const int NT = K / 32;
    float4 ar[4], br[4];

    // prefetch k-tile 0
#pragma unroll
    for (int e = 0; e < 4; e++) {
        ar[e] = *(const float4*)(Abase + (size_t)(e * 32) * K);
        br[e] = *(const float4*)(Bbase + (size_t)(e * 8) * N);
    }

    for (int kt = 0; kt < NT; kt++) {
        // store current tile to smem (tf32-rounded)
#pragma unroll
        for (int e = 0; e < 4; e++) {
            float* ad = &As[(a_row + e * 32) * GA_LD + a_col4];
            ad[0] = to_tf32(ar[e].x); ad[1] = to_tf32(ar[e].y);
            ad[2] = to_tf32(ar[e].z); ad[3] = to_tf32(ar[e].w);
            float* bd = &Bs[(b_row + e * 8) * GB_LD + b_col4];
            bd[0] = to_tf32(br[e].x); bd[1] = to_tf32(br[e].y);
            bd[2] = to_tf32(br[e].z); bd[3] = to_tf32(br[e].w);
        }
        __syncthreads();

        // prefetch next k-tile (overlaps with MMA below)
        if (kt + 1 < NT) {
            const float* An = Abase + (kt + 1) * 32;
            const float* Bn = Bbase + (size_t)((kt + 1) * 32) * N;
#pragma unroll
            for (int e = 0; e < 4; e++) {
                ar[e] = *(const float4*)(An + (size_t)(e * 32) * K);
                br[e] = *(const float4*)(Bn + (size_t)(e * 8) * N);
            }
        }

        // compute: 4 k-steps of 8
#pragma unroll
        for (int kk = 0; kk < 4; kk++) {
            unsigned a[2][4];
#pragma unroll
            for (int mf = 0; mf < 2; mf++) {
                int r = wm + mf * 16 + q4;
                int c0 = kk * 8 + l4;
                a[mf][0] = __float_as_uint(As[(r    ) * GA_LD + c0    ]);
                a[mf][1] = __float_as_uint(As[(r + 8) * GA_LD + c0    ]);
                a[mf][2] = __float_as_uint(As[(r    ) * GA_LD + c0 + 4]);
                a[mf][3] = __float_as_uint(As[(r + 8) * GA_LD + c0 + 4]);
            }
#pragma unroll
            for (int nf = 0; nf < 8; nf++) {
                int n = wn + nf * 8 + q4;
                unsigned b0 = __float_as_uint(Bs[(kk * 8 + l4    ) * GB_LD + n]);
                unsigned b1 = __float_as_uint(Bs[(kk * 8 + l4 + 4) * GB_LD + n]);
                mma_tf32(acc[0][nf], a[0], b0, b1);
                mma_tf32(acc[1][nf], a[1], b0, b1);
            }
        }
        __syncthreads();
    }

    // epilogue: C-frag rows wm+mf*16+q4 (+8), cols wn+nf*8+2*l4 (+1)
#pragma unroll
    for (int mf = 0; mf < 2; mf++) {
        int r = bm0 + wm + mf * 16 + q4;
#pragma unroll
        for (int nf = 0; nf < 8; nf++) {
            int cidx = bn0 + wn + nf * 8 + 2 * l4;
            float2 lo = {acc[mf][nf][0], acc[mf][nf][1]};
            float2 hi = {acc[mf][nf][2], acc[mf][nf][3]};
            *(float2*)(C + (size_t)r * N + cidx)       = lo;
            *(float2*)(C + (size_t)(r + 8) * N + cidx) = hi;
        }
    }
}

// ---------------------------------------------------------------------------
// Tensor-core flash attention (tf32 mma.sync) — unchanged from R4 (passing).
// ---------------------------------------------------------------------------
__global__ __launch_bounds__(128) void attn_tc(const float* __restrict__ Qm,
                                               const float* __restrict__ KVm,
                                               const int* __restrict__ mask,
                                               float* __restrict__ Om)
{
    __shared__ __align__(16) float Ks[64 * KS_LD];
    __shared__ __align__(16) float Vs[64 * VS_LD];

    const int tid  = threadIdx.x;
    const int warp = tid >> 5;
    const int lane = tid & 31;
    const int q4   = lane >> 2;
    const int l4   = lane & 3;
    const int n0   = blockIdx.x * 64;
    const int h    = blockIdx.y;
    const int b    = blockIdx.z;
    const int r0   = warp * 16;

    const float* Qbase  = Qm  + ((size_t)b * SEQN) * DIMC       + h * HD;
    const float* KVbase = KVm + ((size_t)b * SEQM) * (2 * DIMC) + h * HD;

#pragma unroll
    for (int e = 0; e < 8; e++) {
        int i4 = tid + e * 128;
        int i  = i4 >> 4;
        int d4 = (i4 & 15) << 2;
        float4 v = *(const float4*)(Qbase + (size_t)(n0 + i) * DIMC + d4);
        float* dst = &Ks[i * KS_LD + d4];
        dst[0] = to_tf32(v.x); dst[1] = to_tf32(v.y);
        dst[2] = to_tf32(v.z); dst[3] = to_tf32(v.w);
    }
    __syncthreads();

    unsigned qa[8][4];
#pragma unroll
    for (int kt = 0; kt < 8; kt++) {
        int r = r0 + q4;
        qa[kt][0] = __float_as_uint(Ks[(r    ) * KS_LD + kt * 8 + l4    ]);
        qa[kt][1] = __float_as_uint(Ks[(r + 8) * KS_LD + kt * 8 + l4    ]);
        qa[kt][2] = __float_as_uint(Ks[(r    ) * KS_LD + kt * 8 + l4 + 4]);
        qa[kt][3] = __float_as_uint(Ks[(r + 8) * KS_LD + kt * 8 + l4 + 4]);
    }
    __syncthreads();

    float oc[8][4];
#pragma unroll
    for (int nt = 0; nt < 8; nt++)
#pragma unroll
        for (int c = 0; c < 4; c++) oc[nt][c] = 0.0f;
    float mrun_lo = -CUDART_INF_F, mrun_hi = -CUDART_INF_F;
    float lsum_lo = 0.0f, lsum_hi = 0.0f;

    const int i0 = n0 + r0 + q4;
    const int i1 = i0 + 8;
    const int* mrow0 = mask + ((size_t)b * SEQN + i0) * SEQM;
    const int* mrow1 = mask + ((size_t)b * SEQN + i1) * SEQM;

    for (int t = 0; t < SEQM / 64; t++) {
        const int m0 = t * 64;

#pragma unroll
        for (int e = 0; e < 8; e++) {
            int i4 = tid + e * 128;
            int j  = i4 >> 4;
            int d4 = (i4 & 15) << 2;
            const float* row = KVbase + (size_t)(m0 + j) * (2 * DIMC);
            float4 kv = *(const float4*)(row + d4);
            float4 vv = *(const float4*)(row + DIMC + d4);
            float* kd = &Ks[j * KS_LD + d4];
            float* vd = &Vs[j * VS_LD + d4];
            kd[0] = to_tf32(kv.x); kd[1] = to_tf32(kv.y);
            kd[2] = to_tf32(kv.z); kd[3] = to_tf32(kv.w);
            vd[0] = to_tf32(vv.x); vd[1] = to_tf32(vv.y);
            vd[2] = to_tf32(vv.z); vd[3] = to_tf32(vv.w);
        }
        __syncthreads();

        float sc[8][4];
#pragma unroll
        for (int nt = 0; nt < 8; nt++)
#pragma unroll
            for (int c = 0; c < 4; c++) sc[nt][c] = 0.0f;
#pragma unroll
        for (int kt = 0; kt < 8; kt++) {
#pragma unroll
            for (int nt = 0; nt < 8; nt++) {
                int jrow = nt * 8 + q4;
                unsigned b0 = __float_as_uint(Ks[jrow * KS_LD + kt * 8 + l4    ]);
                unsigned b1 = __float_as_uint(Ks[jrow * KS_LD + kt * 8 + l4 + 4]);
                mma_tf32(sc[nt], qa[kt], b0, b1);
            }
        }

#pragma unroll
        for (int nt = 0; nt < 8; nt++) {
            int j = m0 + nt * 8 + 2 * l4;
            int2 ml = *(const int2*)(mrow0 + j);
            int2 mh = *(const int2*)(mrow1 + j);
            sc[nt][0] = ml.x ? sc[nt][0] * ATT_SCALE : -CUDART_INF_F;
            sc[nt][1] = ml.y ? sc[nt][1] * ATT_SCALE : -CUDART_INF_F;
            sc[nt][2] = mh.x ? sc[nt][2] * ATT_SCALE : -CUDART_INF_F;
            sc[nt][3] = mh.y ? sc[nt][3] * ATT_SCALE : -CUDART_INF_F;
        }

        float tml = -CUDART_INF_F, tmh = -CUDART_INF_F;
#pragma unroll
        for (int nt = 0; nt < 8; nt++) {
            tml = fmaxf(tml, fmaxf(sc[nt][0], sc[nt][1]));
            tmh = fmaxf(tmh, fmaxf(sc[nt][2], sc[nt][3]));
        }
        tml = fmaxf(tml, __shfl_xor_sync(0xffffffffu, tml, 1));
        tml = fmaxf(tml, __shfl_xor_sync(0xffffffffu, tml, 2));
        tmh = fmaxf(tmh, __shfl_xor_sync(0xffffffffu, tmh, 1));
        tmh = fmaxf(tmh, __shfl_xor_sync(0xffffffffu, tmh, 2));

        float mnew_lo = fmaxf(mrun_lo, tml);
        float mnew_hi = fmaxf(mrun_hi, tmh);
        bool  inf_lo  = (mnew_lo == -CUDART_INF_F);
        bool  inf_hi  = (mnew_hi == -CUDART_INF_F);

        float ssl = 0.0f, ssh = 0.0f;
#pragma unroll
        for (int nt = 0; nt < 8; nt++) {
            float p0 = inf_lo ? 0.0f : __expf(sc[nt][0] - mnew_lo);
            float p1 = inf_lo ? 0.0f : __expf(sc[nt][1] - mnew_lo);
            float p2 = inf_hi ? 0.0f : __expf(sc[nt][2] - mnew_hi);
            float p3 = inf_hi ? 0.0f : __expf(sc[nt][3] - mnew_hi);
            sc[nt][0] = p0; sc[nt][1] = p1; sc[nt][2] = p2; sc[nt][3] = p3;
            ssl += p0 + p1;
            ssh += p2 + p3;
        }
        ssl += __shfl_xor_sync(0xffffffffu, ssl, 1);
        ssl += __shfl_xor_sync(0xffffffffu, ssl, 2);
        ssh += __shfl_xor_sync(0xffffffffu, ssh, 1);
        ssh += __shfl_xor_sync(0xffffffffu, ssh, 2);

        float alpha_lo = (mrun_lo == -CUDART_INF_F) ? 0.0f : __expf(mrun_lo - mnew_lo);
        float alpha_hi = (mrun_hi == -CUDART_INF_F) ? 0.0f : __expf(mrun_hi - mnew_hi);
        lsum_lo = lsum_lo * alpha_lo + ssl;
        lsum_hi = lsum_hi * alpha_hi + ssh;
        mrun_lo = mnew_lo;
        mrun_hi = mnew_hi;
#pragma unroll
        for (int nt = 0; nt < 8; nt++) {
            oc[nt][0] *= alpha_lo; oc[nt][1] *= alpha_lo;
            oc[nt][2] *= alpha_hi; oc[nt][3] *= alpha_hi;
        }

        const int base = lane & ~3;
        const int src  = base | (l4 >> 1);
        const int src2 = src + 2;
        const bool odd = lane & 1;
#pragma unroll
        for (int kt = 0; kt < 8; kt++) {
            float c0 = sc[kt][0], c1 = sc[kt][1], c2 = sc[kt][2], c3 = sc[kt][3];
            float t00 = __shfl_sync(0xffffffffu, c0, src);
            float t01 = __shfl_sync(0xffffffffu, c1, src);
            float t10 = __shfl_sync(0xffffffffu, c2, src);
            float t11 = __shfl_sync(0xffffffffu, c3, src);
            float t20 = __shfl_sync(0xffffffffu, c0, src2);
            float t21 = __shfl_sync(0xffffffffu, c1, src2);
            float t30 = __shfl_sync(0xffffffffu, c2, src2);
            float t31 = __shfl_sync(0xffffffffu, c3, src2);
            unsigned pa[4];
            pa[0] = tf32_bits(odd ? t01 : t00);
            pa[1] = tf32_bits(odd ? t11 : t10);
            pa[2] = tf32_bits(odd ? t21 : t20);
            pa[3] = tf32_bits(odd ? t31 : t30);
#pragma unroll
            for (int nt = 0; nt < 8; nt++) {
                int vrow = kt * 8 + l4;
                unsigned b0 = __float_as_uint(Vs[(vrow    ) * VS_LD + nt * 8 + q4]);
                unsigned b1 = __float_as_uint(Vs[(vrow + 4) * VS_LD + nt * 8 + q4]);
                mma_tf32(oc[nt], pa, b0, b1);
            }
        }
        __syncthreads();
    }

    float inv_lo = 1.0f / lsum_lo;
    float inv_hi = 1.0f / lsum_hi;
    float* orow0 = Om + (size_t)(b * SEQN + i0) * DIMC + h * HD;
    float* orow1 = Om + (size_t)(b * SEQN + i1) * DIMC + h * HD;
#pragma unroll
    for (int nt = 0; nt < 8; nt++) {
        int d0 = nt * 8 + 2 * l4;
        float2 lo = {oc[nt][0] * inv_lo, oc[nt][1] * inv_lo};
        float2 hi = {oc[nt][2] * inv_hi, oc[nt][3] * inv_hi};
        *(float2*)(orow0 + d0) = lo;
        *(float2*)(orow1 + d0) = hi;
    }
}

// ---------------------------------------------------------------------------
extern "C" void kernel_launch(void* const* d_in, const int* in_sizes, int n_in,
                              void* d_out, int out_size)
{
    const float* x    = (const float*)d_in[0];
    const float* ctx  = (const float*)d_in[1];
    const int*   mask = (const int*)d_in[2];
    const float* Wq   = (const float*)d_in[3];
    const float* Wkv  = (const float*)d_in[4];
    const float* Wo   = (const float*)d_in[5];
    float*       out  = (float*)d_out;

    float *gQ, *gKV, *gO;
    cudaGetSymbolAddress((void**)&gQ,  g_Q);
    cudaGetSymbolAddress((void**)&gKV, g_KV);
    cudaGetSymbolAddress((void**)&gO,  g_O);

    const int Mrows = BATCH * SEQN;   // 8192

    tgemm128<<<dim3(DIMC / 128, Mrows / 128), 256>>>(x, Wq, gQ, Mrows, DIMC, DIMC);
    tgemm128<<<dim3(2 * DIMC / 128, Mrows / 128), 256>>>(ctx, Wkv, gKV, Mrows, 2 * DIMC, DIMC);
    attn_tc<<<dim3(SEQN / 64, NHEADS, BATCH), 128>>>(gQ, gKV, mask, gO);
    tgemm128<<<dim3(DIMC / 128, Mrows / 128), 256>>>(gO, Wo, out, Mrows, DIMC, DIMC);
}

// round 6
// speedup vs baseline: 3.3428x; 1.2578x over previous
#include <cuda_runtime.h>
#include <math_constants.h>
#include <cstddef>
#include <cstdint>

#define DIMC   512
#define HD     64
#define NHEADS 8
#define BATCH  4
#define SEQN   2048
#define SEQM   2048
#define ATT_SCALE 0.125f   // 64^-0.5

#define KS_LD 68   // attention K smem stride (floats)
#define VS_LD 72   // attention V smem stride (floats)

#define GA_LD 36   // gemm A smem stride (128 rows x 32 cols)
#define GB_LD 136  // gemm B smem stride (32 rows x 128 cols)

#define ATTN_SMEM_BYTES ((2 * 64 * KS_LD + 2 * 64 * VS_LD) * 4)

// ---------------- scratch (device globals: allocation-free) ----------------
__device__ float g_Q [BATCH * SEQN * DIMC];        // 16 MB
__device__ float g_KV[BATCH * SEQM * 2 * DIMC];    // 32 MB
__device__ float g_O [BATCH * SEQN * DIMC];        // 16 MB

// ---------------------------------------------------------------------------
// tf32 / async helpers
// ---------------------------------------------------------------------------
__device__ __forceinline__ float to_tf32(float x) {
    unsigned u;
    asm("cvt.rna.tf32.f32 %0, %1;" : "=r"(u) : "f"(x));
    return __uint_as_float(u);
}
__device__ __forceinline__ unsigned tf32_bits(float x) {
    unsigned u;
    asm("cvt.rna.tf32.f32 %0, %1;" : "=r"(u) : "f"(x));
    return u;
}
__device__ __forceinline__ void mma_tf32(float c[4], const unsigned a[4],
                                         unsigned b0, unsigned b1)
{
    asm volatile(
        "mma.sync.aligned.m16n8k8.row.col.f32.tf32.tf32.f32 "
        "{%0,%1,%2,%3},{%4,%5,%6,%7},{%8,%9},{%0,%1,%2,%3};"
        : "+f"(c[0]), "+f"(c[1]), "+f"(c[2]), "+f"(c[3])
        : "r"(a[0]), "r"(a[1]), "r"(a[2]), "r"(a[3]), "r"(b0), "r"(b1));
}
__device__ __forceinline__ void cp_async16(uint32_t smem_addr, const void* gptr) {
    asm volatile("cp.async.cg.shared.global [%0], [%1], 16;"
                 :: "r"(smem_addr), "l"(gptr));
}
__device__ __forceinline__ void cp_commit() {
    asm volatile("cp.async.commit_group;");
}
template <int N>
__device__ __forceinline__ void cp_wait() {
    asm volatile("cp.async.wait_group %0;" :: "n"(N));
}
__device__ __forceinline__ uint32_t smem_u32(const void* p) {
    return (uint32_t)__cvta_generic_to_shared(p);
}

// ---------------------------------------------------------------------------
// tf32 tensor-core GEMM (unchanged from R5, passing): C = A @ B
// ---------------------------------------------------------------------------
__global__ __launch_bounds__(256) void tgemm128(const float* __restrict__ A,
                                                const float* __restrict__ B,
                                                float* __restrict__ C,
                                                int M, int N, int K)
{
    __shared__ __align__(16) float As[128 * GA_LD];
    __shared__ __align__(16) float Bs[32 * GB_LD];

    const int tid  = threadIdx.x;
    const int warp = tid >> 5;
    const int lane = tid & 31;
    const int q4   = lane >> 2;
    const int l4   = lane & 3;
    const int wm   = (warp >> 1) * 32;
    const int wn   = (warp & 1) * 64;
    const int bm0  = blockIdx.y * 128;
    const int bn0  = blockIdx.x * 128;

    const int a_row  = tid >> 3;
    const int a_col4 = (tid & 7) * 4;
    const int b_row  = tid >> 5;
    const int b_col4 = (tid & 31) * 4;

    const float* Abase = A + (size_t)(bm0 + a_row) * K + a_col4;
    const float* Bbase = B + (size_t)b_row * N + bn0 + b_col4;

    float acc[2][8][4];
#pragma unroll
    for (int mf = 0; mf < 2; mf++)
#pragma unroll
        for (int nf = 0; nf < 8; nf++)
#pragma unroll
            for (int c = 0; c < 4; c++) acc[mf][nf][c] = 0.0f;

    const int NT = K / 32;
    float4 ar[4], br[4];

#pragma unroll
    for (int e = 0; e < 4; e++) {
        ar[e] = *(const float4*)(Abase + (size_t)(e * 32) * K);
        br[e] = *(const float4*)(Bbase + (size_t)(e * 8) * N);
    }

    for (int kt = 0; kt < NT; kt++) {
#pragma unroll
        for (int e = 0; e < 4; e++) {
            float* ad = &As[(a_row + e * 32) * GA_LD + a_col4];
            ad[0] = to_tf32(ar[e].x); ad[1] = to_tf32(ar[e].y);
            ad[2] = to_tf32(ar[e].z); ad[3] = to_tf32(ar[e].w);
            float* bd = &Bs[(b_row + e * 8) * GB_LD + b_col4];
            bd[0] = to_tf32(br[e].x); bd[1] = to_tf32(br[e].y);
            bd[2] = to_tf32(br[e].z); bd[3] = to_tf32(br[e].w);
        }
        __syncthreads();

        if (kt + 1 < NT) {
            const float* An = Abase + (kt + 1) * 32;
            const float* Bn = Bbase + (size_t)((kt + 1) * 32) * N;
#pragma unroll
            for (int e = 0; e < 4; e++) {
                ar[e] = *(const float4*)(An + (size_t)(e * 32) * K);
                br[e] = *(const float4*)(Bn + (size_t)(e * 8) * N);
            }
        }

#pragma unroll
        for (int kk = 0; kk < 4; kk++) {
            unsigned a[2][4];
#pragma unroll
            for (int mf = 0; mf < 2; mf++) {
                int r = wm + mf * 16 + q4;
                int c0 = kk * 8 + l4;
                a[mf][0] = __float_as_uint(As[(r    ) * GA_LD + c0    ]);
                a[mf][1] = __float_as_uint(As[(r + 8) * GA_LD + c0    ]);
                a[mf][2] = __float_as_uint(As[(r    ) * GA_LD + c0 + 4]);
                a[mf][3] = __float_as_uint(As[(r + 8) * GA_LD + c0 + 4]);
            }
#pragma unroll
            for (int nf = 0; nf < 8; nf++) {
                int n = wn + nf * 8 + q4;
                unsigned b0 = __float_as_uint(Bs[(kk * 8 + l4    ) * GB_LD + n]);
                unsigned b1 = __float_as_uint(Bs[(kk * 8 + l4 + 4) * GB_LD + n]);
                mma_tf32(acc[0][nf], a[0], b0, b1);
                mma_tf32(acc[1][nf], a[1], b0, b1);
            }
        }
        __syncthreads();
    }

#pragma unroll
    for (int mf = 0; mf < 2; mf++) {
        int r = bm0 + wm + mf * 16 + q4;
#pragma unroll
        for (int nf = 0; nf < 8; nf++) {
            int cidx = bn0 + wn + nf * 8 + 2 * l4;
            float2 lo = {acc[mf][nf][0], acc[mf][nf][1]};
            float2 hi = {acc[mf][nf][2], acc[mf][nf][3]};
            *(float2*)(C + (size_t)r * N + cidx)       = lo;
            *(float2*)(C + (size_t)(r + 8) * N + cidx) = hi;
        }
    }
}

// ---------------------------------------------------------------------------
// Tensor-core flash attention, cp.async double-buffered K/V.
// Raw fp32 staged in smem; cvt.rna applied at fragment read (bit-identical
// to cvt-at-store). Mask prefetched into registers before the QK MMAs.
// Grid: (SEQN/64, NHEADS, BATCH), 128 threads. Dynamic smem 70KB (2 bufs).
// ---------------------------------------------------------------------------
__global__ __launch_bounds__(128) void attn_tc(const float* __restrict__ Qm,
                                               const float* __restrict__ KVm,
                                               const int* __restrict__ mask,
                                               float* __restrict__ Om)
{
    extern __shared__ __align__(16) float smem[];
    float* Ks = smem;                         // 2 x 64 x KS_LD
    float* Vs = smem + 2 * 64 * KS_LD;        // 2 x 64 x VS_LD

    const int tid  = threadIdx.x;
    const int warp = tid >> 5;
    const int lane = tid & 31;
    const int q4   = lane >> 2;
    const int l4   = lane & 3;
    const int n0   = blockIdx.x * 64;
    const int h    = blockIdx.y;
    const int b    = blockIdx.z;
    const int r0   = warp * 16;

    const float* Qbase  = Qm  + ((size_t)b * SEQN) * DIMC       + h * HD;
    const float* KVbase = KVm + ((size_t)b * SEQM) * (2 * DIMC) + h * HD;

    // ---- stage Q (raw fp32) into Ks buf0 ----
#pragma unroll
    for (int e = 0; e < 4; e++) {
        int i4 = tid + e * 128;           // 0..511 float4s
        int i  = i4 >> 3;                 // row 0..63
        int d4 = (i4 & 7) << 3;           // 0,8,...,56 -> two float4? no: (i4&7)*8
        // 64 cols = 16 float4 per row; use 2 float4 per thread-iter
        int c4 = (i4 & 7) * 8;            // 0,8,..,56
        float4 v0 = *(const float4*)(Qbase + (size_t)(n0 + i) * DIMC + c4);
        float4 v1 = *(const float4*)(Qbase + (size_t)(n0 + i) * DIMC + c4 + 4);
        *(float4*)&Ks[i * KS_LD + c4]     = v0;
        *(float4*)&Ks[i * KS_LD + c4 + 4] = v1;
        (void)d4;
    }
    __syncthreads();

    // ---- build Q A-fragments (cvt.rna at read) ----
    unsigned qa[8][4];
#pragma unroll
    for (int kt = 0; kt < 8; kt++) {
        int r = r0 + q4;
        qa[kt][0] = tf32_bits(Ks[(r    ) * KS_LD + kt * 8 + l4    ]);
        qa[kt][1] = tf32_bits(Ks[(r + 8) * KS_LD + kt * 8 + l4    ]);
        qa[kt][2] = tf32_bits(Ks[(r    ) * KS_LD + kt * 8 + l4 + 4]);
        qa[kt][3] = tf32_bits(Ks[(r + 8) * KS_LD + kt * 8 + l4 + 4]);
    }
    __syncthreads();   // Q reads done; buf0 reusable

    // ---- issue tile 0 loads ----
    {
#pragma unroll
        for (int e = 0; e < 8; e++) {
            int i4 = tid + e * 128;
            int j  = i4 >> 4;
            int d4 = (i4 & 15) << 2;
            const float* row = KVbase + (size_t)j * (2 * DIMC) + d4;
            cp_async16(smem_u32(&Ks[j * KS_LD + d4]), row);
            cp_async16(smem_u32(&Vs[j * VS_LD + d4]), row + DIMC);
        }
        cp_commit();
    }

    float oc[8][4];
#pragma unroll
    for (int nt = 0; nt < 8; nt++)
#pragma unroll
        for (int c = 0; c < 4; c++) oc[nt][c] = 0.0f;
    float mrun_lo = -CUDART_INF_F, mrun_hi = -CUDART_INF_F;
    float lsum_lo = 0.0f, lsum_hi = 0.0f;

    const int i0 = n0 + r0 + q4;
    const int i1 = i0 + 8;
    const int* mrow0 = mask + ((size_t)b * SEQN + i0) * SEQM;
    const int* mrow1 = mask + ((size_t)b * SEQN + i1) * SEQM;

    const int T = SEQM / 64;
    for (int t = 0; t < T; t++) {
        const int cur = t & 1;
        // ---- issue next tile into other buffer ----
        if (t + 1 < T) {
            const int nxt = (t + 1) & 1;
            const float* base = KVbase + (size_t)((t + 1) * 64) * (2 * DIMC);
            float* kb = Ks + nxt * 64 * KS_LD;
            float* vb = Vs + nxt * 64 * VS_LD;
#pragma unroll
            for (int e = 0; e < 8; e++) {
                int i4 = tid + e * 128;
                int j  = i4 >> 4;
                int d4 = (i4 & 15) << 2;
                const float* row = base + (size_t)j * (2 * DIMC) + d4;
                cp_async16(smem_u32(&kb[j * KS_LD + d4]), row);
                cp_async16(smem_u32(&vb[j * VS_LD + d4]), row + DIMC);
            }
            cp_commit();
            cp_wait<1>();     // tile t complete (t+1 may be in flight)
        } else {
            cp_commit();
            cp_wait<0>();
        }
        __syncthreads();

        const float* kb = Ks + cur * 64 * KS_LD;
        const float* vb = Vs + cur * 64 * VS_LD;
        const int m0 = t * 64;

        // ---- prefetch mask into registers (overlaps QK MMAs) ----
        int2 ml[8], mh[8];
#pragma unroll
        for (int nt = 0; nt < 8; nt++) {
            int j = m0 + nt * 8 + 2 * l4;
            ml[nt] = *(const int2*)(mrow0 + j);
            mh[nt] = *(const int2*)(mrow1 + j);
        }

        // ---- S = Q K^T ----
        float sc[8][4];
#pragma unroll
        for (int nt = 0; nt < 8; nt++)
#pragma unroll
            for (int c = 0; c < 4; c++) sc[nt][c] = 0.0f;
#pragma unroll
        for (int kt = 0; kt < 8; kt++) {
#pragma unroll
            for (int nt = 0; nt < 8; nt++) {
                int jrow = nt * 8 + q4;
                unsigned b0 = tf32_bits(kb[jrow * KS_LD + kt * 8 + l4    ]);
                unsigned b1 = tf32_bits(kb[jrow * KS_LD + kt * 8 + l4 + 4]);
                mma_tf32(sc[nt], qa[kt], b0, b1);
            }
        }

        // ---- scale + mask ----
#pragma unroll
        for (int nt = 0; nt < 8; nt++) {
            sc[nt][0] = ml[nt].x ? sc[nt][0] * ATT_SCALE : -CUDART_INF_F;
            sc[nt][1] = ml[nt].y ? sc[nt][1] * ATT_SCALE : -CUDART_INF_F;
            sc[nt][2] = mh[nt].x ? sc[nt][2] * ATT_SCALE : -CUDART_INF_F;
            sc[nt][3] = mh[nt].y ? sc[nt][3] * ATT_SCALE : -CUDART_INF_F;
        }

        // ---- online softmax ----
        float tml = -CUDART_INF_F, tmh = -CUDART_INF_F;
#pragma unroll
        for (int nt = 0; nt < 8; nt++) {
            tml = fmaxf(tml, fmaxf(sc[nt][0], sc[nt][1]));
            tmh = fmaxf(tmh, fmaxf(sc[nt][2], sc[nt][3]));
        }
        tml = fmaxf(tml, __shfl_xor_sync(0xffffffffu, tml, 1));
        tml = fmaxf(tml, __shfl_xor_sync(0xffffffffu, tml, 2));
        tmh = fmaxf(tmh, __shfl_xor_sync(0xffffffffu, tmh, 1));
        tmh = fmaxf(tmh, __shfl_xor_sync(0xffffffffu, tmh, 2));

        float mnew_lo = fmaxf(mrun_lo, tml);
        float mnew_hi = fmaxf(mrun_hi, tmh);
        bool  inf_lo  = (mnew_lo == -CUDART_INF_F);
        bool  inf_hi  = (mnew_hi == -CUDART_INF_F);

        float ssl = 0.0f, ssh = 0.0f;
#pragma unroll
        for (int nt = 0; nt < 8; nt++) {
            float p0 = inf_lo ? 0.0f : __expf(sc[nt][0] - mnew_lo);
            float p1 = inf_lo ? 0.0f : __expf(sc[nt][1] - mnew_lo);
            float p2 = inf_hi ? 0.0f : __expf(sc[nt][2] - mnew_hi);
            float p3 = inf_hi ? 0.0f : __expf(sc[nt][3] - mnew_hi);
            sc[nt][0] = p0; sc[nt][1] = p1; sc[nt][2] = p2; sc[nt][3] = p3;
            ssl += p0 + p1;
            ssh += p2 + p3;
        }
        ssl += __shfl_xor_sync(0xffffffffu, ssl, 1);
        ssl += __shfl_xor_sync(0xffffffffu, ssl, 2);
        ssh += __shfl_xor_sync(0xffffffffu, ssh, 1);
        ssh += __shfl_xor_sync(0xffffffffu, ssh, 2);

        float alpha_lo = (mrun_lo == -CUDART_INF_F) ? 0.0f : __expf(mrun_lo - mnew_lo);
        float alpha_hi = (mrun_hi == -CUDART_INF_F) ? 0.0f : __expf(mrun_hi - mnew_hi);
        lsum_lo = lsum_lo * alpha_lo + ssl;
        lsum_hi = lsum_hi * alpha_hi + ssh;
        mrun_lo = mnew_lo;
        mrun_hi = mnew_hi;
#pragma unroll
        for (int nt = 0; nt < 8; nt++) {
            oc[nt][0] *= alpha_lo; oc[nt][1] *= alpha_lo;
            oc[nt][2] *= alpha_hi; oc[nt][3] *= alpha_hi;
        }

        // ---- O += P @ V ----
        const int base2 = lane & ~3;
        const int src  = base2 | (l4 >> 1);
        const int src2 = src + 2;
        const bool odd = lane & 1;
#pragma unroll
        for (int kt = 0; kt < 8; kt++) {
            float c0 = sc[kt][0], c1 = sc[kt][1], c2 = sc[kt][2], c3 = sc[kt][3];
            float t00 = __shfl_sync(0xffffffffu, c0, src);
            float t01 = __shfl_sync(0xffffffffu, c1, src);
            float t10 = __shfl_sync(0xffffffffu, c2, src);
            float t11 = __shfl_sync(0xffffffffu, c3, src);
            float t20 = __shfl_sync(0xffffffffu, c0, src2);
            float t21 = __shfl_sync(0xffffffffu, c1, src2);
            float t30 = __shfl_sync(0xffffffffu, c2, src2);
            float t31 = __shfl_sync(0xffffffffu, c3, src2);
            unsigned pa[4];
            pa[0] = tf32_bits(odd ? t01 : t00);
            pa[1] = tf32_bits(odd ? t11 : t10);
            pa[2] = tf32_bits(odd ? t21 : t20);
            pa[3] = tf32_bits(odd ? t31 : t30);
#pragma unroll
            for (int nt = 0; nt < 8; nt++) {
                int vrow = kt * 8 + l4;
                unsigned b0 = tf32_bits(vb[(vrow    ) * VS_LD + nt * 8 + q4]);
                unsigned b1 = tf32_bits(vb[(vrow + 4) * VS_LD + nt * 8 + q4]);
                mma_tf32(oc[nt], pa, b0, b1);
            }
        }
        __syncthreads();   // all reads of cur done before tile t+2 overwrites it
    }

    // ---- normalize + write O ----
    float inv_lo = 1.0f / lsum_lo;
    float inv_hi = 1.0f / lsum_hi;
    float* orow0 = Om + (size_t)(b * SEQN + i0) * DIMC + h * HD;
    float* orow1 = Om + (size_t)(b * SEQN + i1) * DIMC + h * HD;
#pragma unroll
    for (int nt = 0; nt < 8; nt++) {
        int d0 = nt * 8 + 2 * l4;
        float2 lo = {oc[nt][0] * inv_lo, oc[nt][1] * inv_lo};
        float2 hi = {oc[nt][2] * inv_hi, oc[nt][3] * inv_hi};
        *(float2*)(orow0 + d0) = lo;
        *(float2*)(orow1 + d0) = hi;
    }
}

// ---------------------------------------------------------------------------
extern "C" void kernel_launch(void* const* d_in, const int* in_sizes, int n_in,
                              void* d_out, int out_size)
{
    const float* x    = (const float*)d_in[0];
    const float* ctx  = (const float*)d_in[1];
    const int*   mask = (const int*)d_in[2];
    const float* Wq   = (const float*)d_in[3];
    const float* Wkv  = (const float*)d_in[4];
    const float* Wo   = (const float*)d_in[5];
    float*       out  = (float*)d_out;

    float *gQ, *gKV, *gO;
    cudaGetSymbolAddress((void**)&gQ,  g_Q);
    cudaGetSymbolAddress((void**)&gKV, g_KV);
    cudaGetSymbolAddress((void**)&gO,  g_O);

    cudaFuncSetAttribute(attn_tc, cudaFuncAttributeMaxDynamicSharedMemorySize,
                         ATTN_SMEM_BYTES);

    const int Mrows = BATCH * SEQN;   // 8192

    tgemm128<<<dim3(DIMC / 128, Mrows / 128), 256>>>(x, Wq, gQ, Mrows, DIMC, DIMC);
    tgemm128<<<dim3(2 * DIMC / 128, Mrows / 128), 256>>>(ctx, Wkv, gKV, Mrows, 2 * DIMC, DIMC);
    attn_tc<<<dim3(SEQN / 64, NHEADS, BATCH), 128, ATTN_SMEM_BYTES>>>(gQ, gKV, mask, gO);
    tgemm128<<<dim3(DIMC / 128, Mrows / 128), 256>>>(gO, Wo, out, Mrows, DIMC, DIMC);
}

// round 7
// speedup vs baseline: 3.4256x; 1.0248x over previous
#include <cuda_runtime.h>
#include <math_constants.h>
#include <cstddef>
#include <cstdint>

#define DIMC   512
#define HD     64
#define NHEADS 8
#define BATCH  4
#define SEQN   2048
#define SEQM   2048
#define ATT_SCALE 0.125f   // 64^-0.5

#define KS_LD 68   // attention K smem stride (floats)
#define VS_LD 72   // attention V smem stride (floats)

#define GA_LD 36   // gemm A smem stride
#define GB_LD 136  // gemm B smem stride

#define ATTN_SMEM_BYTES ((2 * 64 * KS_LD + 2 * 64 * VS_LD) * 4)
#define MASK_WORDS (BATCH * SEQN * (SEQM / 32))

// ---------------- scratch (device globals: allocation-free) ----------------
__device__ float    g_Q   [BATCH * SEQN * DIMC];       // 16 MB
__device__ float    g_KV  [BATCH * SEQM * 2 * DIMC];   // 32 MB
__device__ float    g_O   [BATCH * SEQN * DIMC];       // 16 MB
__device__ uint32_t g_mask[MASK_WORDS];                // 2 MB bitpacked mask

// ---------------------------------------------------------------------------
// tf32 / async helpers
// ---------------------------------------------------------------------------
__device__ __forceinline__ float to_tf32(float x) {
    unsigned u;
    asm("cvt.rna.tf32.f32 %0, %1;" : "=r"(u) : "f"(x));
    return __uint_as_float(u);
}
__device__ __forceinline__ unsigned tf32_bits(float x) {
    unsigned u;
    asm("cvt.rna.tf32.f32 %0, %1;" : "=r"(u) : "f"(x));
    return u;
}
__device__ __forceinline__ void mma_tf32(float c[4], const unsigned a[4],
                                         unsigned b0, unsigned b1)
{
    asm volatile(
        "mma.sync.aligned.m16n8k8.row.col.f32.tf32.tf32.f32 "
        "{%0,%1,%2,%3},{%4,%5,%6,%7},{%8,%9},{%0,%1,%2,%3};"
        : "+f"(c[0]), "+f"(c[1]), "+f"(c[2]), "+f"(c[3])
        : "r"(a[0]), "r"(a[1]), "r"(a[2]), "r"(a[3]), "r"(b0), "r"(b1));
}
__device__ __forceinline__ void cp_async16(uint32_t smem_addr, const void* gptr) {
    asm volatile("cp.async.cg.shared.global [%0], [%1], 16;"
                 :: "r"(smem_addr), "l"(gptr));
}
__device__ __forceinline__ void cp_commit() {
    asm volatile("cp.async.commit_group;");
}
template <int N>
__device__ __forceinline__ void cp_wait() {
    asm volatile("cp.async.wait_group %0;" :: "n"(N));
}
__device__ __forceinline__ uint32_t smem_u32(const void* p) {
    return (uint32_t)__cvta_generic_to_shared(p);
}

// ---------------------------------------------------------------------------
// Mask bit-pack: 32 int32 -> 1 uint32 via ballot. n must be multiple of 32.
// ---------------------------------------------------------------------------
__global__ __launch_bounds__(256) void pack_mask(const int* __restrict__ mask,
                                                 uint32_t* __restrict__ bm, int n)
{
    int idx = blockIdx.x * blockDim.x + threadIdx.x;
    if (idx < n) {
        unsigned bal = __ballot_sync(0xffffffffu, mask[idx] != 0);
        if ((threadIdx.x & 31) == 0) bm[idx >> 5] = bal;
    }
}

// ---------------------------------------------------------------------------
// tf32 tensor-core GEMM (unchanged, passing): C = A @ B
// ---------------------------------------------------------------------------
__global__ __launch_bounds__(256) void tgemm128(const float* __restrict__ A,
                                                const float* __restrict__ B,
                                                float* __restrict__ C,
                                                int M, int N, int K)
{
    __shared__ __align__(16) float As[128 * GA_LD];
    __shared__ __align__(16) float Bs[32 * GB_LD];

    const int tid  = threadIdx.x;
    const int warp = tid >> 5;
    const int lane = tid & 31;
    const int q4   = lane >> 2;
    const int l4   = lane & 3;
    const int wm   = (warp >> 1) * 32;
    const int wn   = (warp & 1) * 64;
    const int bm0  = blockIdx.y * 128;
    const int bn0  = blockIdx.x * 128;

    const int a_row  = tid >> 3;
    const int a_col4 = (tid & 7) * 4;
    const int b_row  = tid >> 5;
    const int b_col4 = (tid & 31) * 4;

    const float* Abase = A + (size_t)(bm0 + a_row) * K + a_col4;
    const float* Bbase = B + (size_t)b_row * N + bn0 + b_col4;

    float acc[2][8][4];
#pragma unroll
    for (int mf = 0; mf < 2; mf++)
#pragma unroll
        for (int nf = 0; nf < 8; nf++)
#pragma unroll
            for (int c = 0; c < 4; c++) acc[mf][nf][c] = 0.0f;

    const int NT = K / 32;
    float4 ar[4], br[4];

#pragma unroll
    for (int e = 0; e < 4; e++) {
        ar[e] = *(const float4*)(Abase + (size_t)(e * 32) * K);
        br[e] = *(const float4*)(Bbase + (size_t)(e * 8) * N);
    }

    for (int kt = 0; kt < NT; kt++) {
#pragma unroll
        for (int e = 0; e < 4; e++) {
            float* ad = &As[(a_row + e * 32) * GA_LD + a_col4];
            ad[0] = to_tf32(ar[e].x); ad[1] = to_tf32(ar[e].y);
            ad[2] = to_tf32(ar[e].z); ad[3] = to_tf32(ar[e].w);
            float* bd = &Bs[(b_row + e * 8) * GB_LD + b_col4];
            bd[0] = to_tf32(br[e].x); bd[1] = to_tf32(br[e].y);
            bd[2] = to_tf32(br[e].z); bd[3] = to_tf32(br[e].w);
        }
        __syncthreads();

        if (kt + 1 < NT) {
            const float* An = Abase + (kt + 1) * 32;
            const float* Bn = Bbase + (size_t)((kt + 1) * 32) * N;
#pragma unroll
            for (int e = 0; e < 4; e++) {
                ar[e] = *(const float4*)(An + (size_t)(e * 32) * K);
                br[e] = *(const float4*)(Bn + (size_t)(e * 8) * N);
            }
        }

#pragma unroll
        for (int kk = 0; kk < 4; kk++) {
            unsigned a[2][4];
#pragma unroll
            for (int mf = 0; mf < 2; mf++) {
                int r = wm + mf * 16 + q4;
                int c0 = kk * 8 + l4;
                a[mf][0] = __float_as_uint(As[(r    ) * GA_LD + c0    ]);
                a[mf][1] = __float_as_uint(As[(r + 8) * GA_LD + c0    ]);
                a[mf][2] = __float_as_uint(As[(r    ) * GA_LD + c0 + 4]);
                a[mf][3] = __float_as_uint(As[(r + 8) * GA_LD + c0 + 4]);
            }
#pragma unroll
            for (int nf = 0; nf < 8; nf++) {
                int n = wn + nf * 8 + q4;
                unsigned b0 = __float_as_uint(Bs[(kk * 8 + l4    ) * GB_LD + n]);
                unsigned b1 = __float_as_uint(Bs[(kk * 8 + l4 + 4) * GB_LD + n]);
                mma_tf32(acc[0][nf], a[0], b0, b1);
                mma_tf32(acc[1][nf], a[1], b0, b1);
            }
        }
        __syncthreads();
    }

#pragma unroll
    for (int mf = 0; mf < 2; mf++) {
        int r = bm0 + wm + mf * 16 + q4;
#pragma unroll
        for (int nf = 0; nf < 8; nf++) {
            int cidx = bn0 + wn + nf * 8 + 2 * l4;
            float2 lo = {acc[mf][nf][0], acc[mf][nf][1]};
            float2 hi = {acc[mf][nf][2], acc[mf][nf][3]};
            *(float2*)(C + (size_t)r * N + cidx)       = lo;
            *(float2*)(C + (size_t)(r + 8) * N + cidx) = hi;
        }
    }
}

// ---------------------------------------------------------------------------
// Tensor-core flash attention v3:
//  - 128 queries/CTA, 4 warps, 32 queries/warp (two m16 fragments, mf=0,1)
//    -> K/V smem reads amortized over 2x MMA work.
//  - cp.async double-buffered K/V (raw fp32; cvt.rna at fragment read).
//  - bitpacked mask (uint2 per row-pair per tile).
// Grid: (SEQN/128, NHEADS, BATCH), 128 threads.
// ---------------------------------------------------------------------------
__global__ __launch_bounds__(128) void attn_tc(const float* __restrict__ Qm,
                                               const float* __restrict__ KVm,
                                               const uint32_t* __restrict__ bmask,
                                               float* __restrict__ Om)
{
    extern __shared__ __align__(16) float smem[];
    float* Ks = smem;                         // 2 x 64 x KS_LD (= 128 x KS_LD)
    float* Vs = smem + 2 * 64 * KS_LD;        // 2 x 64 x VS_LD

    const int tid  = threadIdx.x;
    const int warp = tid >> 5;
    const int lane = tid & 31;
    const int q4   = lane >> 2;
    const int l4   = lane & 3;
    const int n0   = blockIdx.x * 128;
    const int h    = blockIdx.y;
    const int b    = blockIdx.z;
    const int r0   = warp * 32;               // warp's first query row (of 128)

    const float* Qbase  = Qm  + ((size_t)b * SEQN) * DIMC       + h * HD;
    const float* KVbase = KVm + ((size_t)b * SEQM) * (2 * DIMC) + h * HD;

    // ---- stage Q (raw fp32, 128 rows x 64) into the Ks double-buffer region ----
#pragma unroll
    for (int e = 0; e < 16; e++) {
        int i4 = tid + e * 128;               // 0..2047 float4s
        int i  = i4 >> 4;                     // row 0..127
        int c4 = (i4 & 15) << 2;              // 0..60
        float4 v = *(const float4*)(Qbase + (size_t)(n0 + i) * DIMC + c4);
        *(float4*)&Ks[i * KS_LD + c4] = v;
    }
    __syncthreads();

    // ---- build Q A-fragments (cvt at read): qa[kt][mf] ----
    unsigned qa[8][2][4];
#pragma unroll
    for (int kt = 0; kt < 8; kt++) {
#pragma unroll
        for (int mf = 0; mf < 2; mf++) {
            int r = r0 + mf * 16 + q4;
            qa[kt][mf][0] = tf32_bits(Ks[(r    ) * KS_LD + kt * 8 + l4    ]);
            qa[kt][mf][1] = tf32_bits(Ks[(r + 8) * KS_LD + kt * 8 + l4    ]);
            qa[kt][mf][2] = tf32_bits(Ks[(r    ) * KS_LD + kt * 8 + l4 + 4]);
            qa[kt][mf][3] = tf32_bits(Ks[(r + 8) * KS_LD + kt * 8 + l4 + 4]);
        }
    }
    __syncthreads();   // Q reads done; Ks region reusable for K tiles

    // ---- issue tile 0 K/V loads ----
#pragma unroll
    for (int e = 0; e < 8; e++) {
        int i4 = tid + e * 128;
        int j  = i4 >> 4;
        int d4 = (i4 & 15) << 2;
        const float* row = KVbase + (size_t)j * (2 * DIMC) + d4;
        cp_async16(smem_u32(&Ks[j * KS_LD + d4]), row);
        cp_async16(smem_u32(&Vs[j * VS_LD + d4]), row + DIMC);
    }
    cp_commit();

    float oc[2][8][4];
#pragma unroll
    for (int mf = 0; mf < 2; mf++)
#pragma unroll
        for (int nt = 0; nt < 8; nt++)
#pragma unroll
            for (int c = 0; c < 4; c++) oc[mf][nt][c] = 0.0f;
    float mrun_lo[2] = {-CUDART_INF_F, -CUDART_INF_F};
    float mrun_hi[2] = {-CUDART_INF_F, -CUDART_INF_F};
    float lsum_lo[2] = {0.0f, 0.0f};
    float lsum_hi[2] = {0.0f, 0.0f};

    // mask word pointers: 4 rows per thread (mf x {lo,hi}), SEQM/32=64 words/row
    const uint32_t* mp[2][2];
#pragma unroll
    for (int mf = 0; mf < 2; mf++) {
        int ilo = n0 + r0 + mf * 16 + q4;
        mp[mf][0] = bmask + ((size_t)(b * SEQN + ilo    ) * (SEQM / 32));
        mp[mf][1] = bmask + ((size_t)(b * SEQN + ilo + 8) * (SEQM / 32));
    }

    const int T = SEQM / 64;
    for (int t = 0; t < T; t++) {
        const int cur = t & 1;
        if (t + 1 < T) {
            const int nxt = (t + 1) & 1;
            const float* base = KVbase + (size_t)((t + 1) * 64) * (2 * DIMC);
            float* kb = Ks + nxt * 64 * KS_LD;
            float* vb = Vs + nxt * 64 * VS_LD;
#pragma unroll
            for (int e = 0; e < 8; e++) {
                int i4 = tid + e * 128;
                int j  = i4 >> 4;
                int d4 = (i4 & 15) << 2;
                const float* row = base + (size_t)j * (2 * DIMC) + d4;
                cp_async16(smem_u32(&kb[j * KS_LD + d4]), row);
                cp_async16(smem_u32(&vb[j * VS_LD + d4]), row + DIMC);
            }
            cp_commit();
            cp_wait<1>();
        } else {
            cp_commit();
            cp_wait<0>();
        }
        __syncthreads();

        const float* kb = Ks + cur * 64 * KS_LD;
        const float* vb = Vs + cur * 64 * VS_LD;

        // ---- prefetch bitmask words (overlaps QK MMAs) ----
        uint2 mw[2][2];
#pragma unroll
        for (int mf = 0; mf < 2; mf++) {
            mw[mf][0] = *(const uint2*)(mp[mf][0] + t * 2);
            mw[mf][1] = *(const uint2*)(mp[mf][1] + t * 2);
        }

        // ---- S = Q K^T ----
        float sc[2][8][4];
#pragma unroll
        for (int mf = 0; mf < 2; mf++)
#pragma unroll
            for (int nt = 0; nt < 8; nt++)
#pragma unroll
                for (int c = 0; c < 4; c++) sc[mf][nt][c] = 0.0f;
#pragma unroll
        for (int kt = 0; kt < 8; kt++) {
#pragma unroll
            for (int nt = 0; nt < 8; nt++) {
                int jrow = nt * 8 + q4;
                unsigned b0 = tf32_bits(kb[jrow * KS_LD + kt * 8 + l4    ]);
                unsigned b1 = tf32_bits(kb[jrow * KS_LD + kt * 8 + l4 + 4]);
                mma_tf32(sc[0][nt], qa[kt][0], b0, b1);
                mma_tf32(sc[1][nt], qa[kt][1], b0, b1);
            }
        }

        // ---- scale + mask (bit test) ----
#pragma unroll
        for (int mf = 0; mf < 2; mf++) {
#pragma unroll
            for (int nt = 0; nt < 8; nt++) {
                uint32_t wlo = (nt < 4) ? mw[mf][0].x : mw[mf][0].y;
                uint32_t whi = (nt < 4) ? mw[mf][1].x : mw[mf][1].y;
                int bit = (nt * 8 + 2 * l4) & 31;
                sc[mf][nt][0] = ((wlo >> bit) & 1u)       ? sc[mf][nt][0] * ATT_SCALE : -CUDART_INF_F;
                sc[mf][nt][1] = ((wlo >> (bit + 1)) & 1u) ? sc[mf][nt][1] * ATT_SCALE : -CUDART_INF_F;
                sc[mf][nt][2] = ((whi >> bit) & 1u)       ? sc[mf][nt][2] * ATT_SCALE : -CUDART_INF_F;
                sc[mf][nt][3] = ((whi >> (bit + 1)) & 1u) ? sc[mf][nt][3] * ATT_SCALE : -CUDART_INF_F;
            }
        }

        // ---- online softmax (per mf, two rows per thread) ----
#pragma unroll
        for (int mf = 0; mf < 2; mf++) {
            float tml = -CUDART_INF_F, tmh = -CUDART_INF_F;
#pragma unroll
            for (int nt = 0; nt < 8; nt++) {
                tml = fmaxf(tml, fmaxf(sc[mf][nt][0], sc[mf][nt][1]));
                tmh = fmaxf(tmh, fmaxf(sc[mf][nt][2], sc[mf][nt][3]));
            }
            tml = fmaxf(tml, __shfl_xor_sync(0xffffffffu, tml, 1));
            tml = fmaxf(tml, __shfl_xor_sync(0xffffffffu, tml, 2));
            tmh = fmaxf(tmh, __shfl_xor_sync(0xffffffffu, tmh, 1));
            tmh = fmaxf(tmh, __shfl_xor_sync(0xffffffffu, tmh, 2));

            float mnew_lo = fmaxf(mrun_lo[mf], tml);
            float mnew_hi = fmaxf(mrun_hi[mf], tmh);
            bool  inf_lo  = (mnew_lo == -CUDART_INF_F);
            bool  inf_hi  = (mnew_hi == -CUDART_INF_F);

            float ssl = 0.0f, ssh = 0.0f;
#pragma unroll
            for (int nt = 0; nt < 8; nt++) {
                float p0 = inf_lo ? 0.0f : __expf(sc[mf][nt][0] - mnew_lo);
                float p1 = inf_lo ? 0.0f : __expf(sc[mf][nt][1] - mnew_lo);
                float p2 = inf_hi ? 0.0f : __expf(sc[mf][nt][2] - mnew_hi);
                float p3 = inf_hi ? 0.0f : __expf(sc[mf][nt][3] - mnew_hi);
                sc[mf][nt][0] = p0; sc[mf][nt][1] = p1;
                sc[mf][nt][2] = p2; sc[mf][nt][3] = p3;
                ssl += p0 + p1;
                ssh += p2 + p3;
            }
            ssl += __shfl_xor_sync(0xffffffffu, ssl, 1);
            ssl += __shfl_xor_sync(0xffffffffu, ssl, 2);
            ssh += __shfl_xor_sync(0xffffffffu, ssh, 1);
            ssh += __shfl_xor_sync(0xffffffffu, ssh, 2);

            float alpha_lo = (mrun_lo[mf] == -CUDART_INF_F) ? 0.0f : __expf(mrun_lo[mf] - mnew_lo);
            float alpha_hi = (mrun_hi[mf] == -CUDART_INF_F) ? 0.0f : __expf(mrun_hi[mf] - mnew_hi);
            lsum_lo[mf] = lsum_lo[mf] * alpha_lo + ssl;
            lsum_hi[mf] = lsum_hi[mf] * alpha_hi + ssh;
            mrun_lo[mf] = mnew_lo;
            mrun_hi[mf] = mnew_hi;
#pragma unroll
            for (int nt = 0; nt < 8; nt++) {
                oc[mf][nt][0] *= alpha_lo; oc[mf][nt][1] *= alpha_lo;
                oc[mf][nt][2] *= alpha_hi; oc[mf][nt][3] *= alpha_hi;
            }
        }

        // ---- O += P @ V (P C-frag -> A-frag via shuffles; V frags shared by mf) ----
        const int base2 = lane & ~3;
        const int src  = base2 | (l4 >> 1);
        const int src2 = src + 2;
        const bool odd = lane & 1;
#pragma unroll
        for (int kt = 0; kt < 8; kt++) {
            unsigned pa[2][4];
#pragma unroll
            for (int mf = 0; mf < 2; mf++) {
                float c0 = sc[mf][kt][0], c1 = sc[mf][kt][1];
                float c2 = sc[mf][kt][2], c3 = sc[mf][kt][3];
                float t00 = __shfl_sync(0xffffffffu, c0, src);
                float t01 = __shfl_sync(0xffffffffu, c1, src);
                float t10 = __shfl_sync(0xffffffffu, c2, src);
                float t11 = __shfl_sync(0xffffffffu, c3, src);
                float t20 = __shfl_sync(0xffffffffu, c0, src2);
                float t21 = __shfl_sync(0xffffffffu, c1, src2);
                float t30 = __shfl_sync(0xffffffffu, c2, src2);
                float t31 = __shfl_sync(0xffffffffu, c3, src2);
                pa[mf][0] = tf32_bits(odd ? t01 : t00);
                pa[mf][1] = tf32_bits(odd ? t11 : t10);
                pa[mf][2] = tf32_bits(odd ? t21 : t20);
                pa[mf][3] = tf32_bits(odd ? t31 : t30);
            }
#pragma unroll
            for (int nt = 0; nt < 8; nt++) {
                int vrow = kt * 8 + l4;
                unsigned b0 = tf32_bits(vb[(vrow    ) * VS_LD + nt * 8 + q4]);
                unsigned b1 = tf32_bits(vb[(vrow + 4) * VS_LD + nt * 8 + q4]);
                mma_tf32(oc[0][nt], pa[0], b0, b1);
                mma_tf32(oc[1][nt], pa[1], b0, b1);
            }
        }
        __syncthreads();
    }

    // ---- normalize + write O ----
#pragma unroll
    for (int mf = 0; mf < 2; mf++) {
        float inv_lo = 1.0f / lsum_lo[mf];
        float inv_hi = 1.0f / lsum_hi[mf];
        int ilo = n0 + r0 + mf * 16 + q4;
        float* orow0 = Om + (size_t)(b * SEQN + ilo    ) * DIMC + h * HD;
        float* orow1 = Om + (size_t)(b * SEQN + ilo + 8) * DIMC + h * HD;
#pragma unroll
        for (int nt = 0; nt < 8; nt++) {
            int d0 = nt * 8 + 2 * l4;
            float2 lo = {oc[mf][nt][0] * inv_lo, oc[mf][nt][1] * inv_lo};
            float2 hi = {oc[mf][nt][2] * inv_hi, oc[mf][nt][3] * inv_hi};
            *(float2*)(orow0 + d0) = lo;
            *(float2*)(orow1 + d0) = hi;
        }
    }
}

// ---------------------------------------------------------------------------
extern "C" void kernel_launch(void* const* d_in, const int* in_sizes, int n_in,
                              void* d_out, int out_size)
{
    const float* x    = (const float*)d_in[0];
    const float* ctx  = (const float*)d_in[1];
    const int*   mask = (const int*)d_in[2];
    const float* Wq   = (const float*)d_in[3];
    const float* Wkv  = (const float*)d_in[4];
    const float* Wo   = (const float*)d_in[5];
    float*       out  = (float*)d_out;

    float *gQ, *gKV, *gO;
    uint32_t* gM;
    cudaGetSymbolAddress((void**)&gQ,  g_Q);
    cudaGetSymbolAddress((void**)&gKV, g_KV);
    cudaGetSymbolAddress((void**)&gO,  g_O);
    cudaGetSymbolAddress((void**)&gM,  g_mask);

    cudaFuncSetAttribute(attn_tc, cudaFuncAttributeMaxDynamicSharedMemorySize,
                         ATTN_SMEM_BYTES);

    const int Mrows = BATCH * SEQN;   // 8192
    const int mask_n = BATCH * SEQN * SEQM;

    pack_mask<<<mask_n / 256, 256>>>(mask, gM, mask_n);
    tgemm128<<<dim3(DIMC / 128, Mrows / 128), 256>>>(x, Wq, gQ, Mrows, DIMC, DIMC);
    tgemm128<<<dim3(2 * DIMC / 128, Mrows / 128), 256>>>(ctx, Wkv, gKV, Mrows, 2 * DIMC, DIMC);
    attn_tc<<<dim3(SEQN / 128, NHEADS, BATCH), 128, ATTN_SMEM_BYTES>>>(gQ, gKV, gM, gO);
    tgemm128<<<dim3(DIMC / 128, Mrows / 128), 256>>>(gO, Wo, out, Mrows, DIMC, DIMC);
}

// round 8
// speedup vs baseline: 3.6814x; 1.0747x over previous
#include <cuda_runtime.h>
#include <math_constants.h>
#include <cstddef>
#include <cstdint>

#define DIMC   512
#define HD     64
#define NHEADS 8
#define BATCH  4
#define SEQN   2048
#define SEQM   2048
#define ATT_SCALE 0.125f   // 64^-0.5

#define KS_LD 68   // attention K smem stride (floats)
#define VS_LD 72   // attention V smem stride (floats)

#define GA_LD 36   // gemm A smem stride
#define GB_LD 136  // gemm B smem stride

#define ATTN_SMEM_BYTES ((2 * 64 * KS_LD + 2 * 64 * VS_LD) * 4)
#define MASK_WORDS (BATCH * SEQN * (SEQM / 32))

// ---------------- scratch (device globals: allocation-free) ----------------
__device__ float    g_Q   [BATCH * SEQN * DIMC];       // 16 MB (tf32-rounded)
__device__ float    g_KV  [BATCH * SEQM * 2 * DIMC];   // 32 MB (tf32-rounded)
__device__ float    g_O   [BATCH * SEQN * DIMC];       // 16 MB
__device__ uint32_t g_mask[MASK_WORDS];                // 2 MB bitpacked mask

// ---------------------------------------------------------------------------
// tf32 / async helpers
// ---------------------------------------------------------------------------
__device__ __forceinline__ float to_tf32(float x) {
    unsigned u;
    asm("cvt.rna.tf32.f32 %0, %1;" : "=r"(u) : "f"(x));
    return __uint_as_float(u);
}
__device__ __forceinline__ unsigned tf32_bits(float x) {
    unsigned u;
    asm("cvt.rna.tf32.f32 %0, %1;" : "=r"(u) : "f"(x));
    return u;
}
__device__ __forceinline__ void mma_tf32(float c[4], const unsigned a[4],
                                         unsigned b0, unsigned b1)
{
    asm volatile(
        "mma.sync.aligned.m16n8k8.row.col.f32.tf32.tf32.f32 "
        "{%0,%1,%2,%3},{%4,%5,%6,%7},{%8,%9},{%0,%1,%2,%3};"
        : "+f"(c[0]), "+f"(c[1]), "+f"(c[2]), "+f"(c[3])
        : "r"(a[0]), "r"(a[1]), "r"(a[2]), "r"(a[3]), "r"(b0), "r"(b1));
}
__device__ __forceinline__ void cp_async16(uint32_t smem_addr, const void* gptr) {
    asm volatile("cp.async.cg.shared.global [%0], [%1], 16;"
                 :: "r"(smem_addr), "l"(gptr));
}
__device__ __forceinline__ void cp_commit() {
    asm volatile("cp.async.commit_group;");
}
template <int N>
__device__ __forceinline__ void cp_wait() {
    asm volatile("cp.async.wait_group %0;" :: "n"(N));
}
__device__ __forceinline__ uint32_t smem_u32(const void* p) {
    return (uint32_t)__cvta_generic_to_shared(p);
}

// ---------------------------------------------------------------------------
// Mask bit-pack: 32 int32 -> 1 uint32 via ballot.
// ---------------------------------------------------------------------------
__global__ __launch_bounds__(256) void pack_mask(const int* __restrict__ mask,
                                                 uint32_t* __restrict__ bm, int n)
{
    int idx = blockIdx.x * blockDim.x + threadIdx.x;
    if (idx < n) {
        unsigned bal = __ballot_sync(0xffffffffu, mask[idx] != 0);
        if ((threadIdx.x & 31) == 0) bm[idx >> 5] = bal;
    }
}

// ---------------------------------------------------------------------------
// tf32 tensor-core GEMM: C = A @ B.
// RND: round outputs to tf32 (for tensors consumed by attention MMAs) —
// bit-identical to rounding at the consumer, but removes cvts from the
// attention hot loop.
// ---------------------------------------------------------------------------
template <bool RND>
__global__ __launch_bounds__(256) void tgemm128(const float* __restrict__ A,
                                                const float* __restrict__ B,
                                                float* __restrict__ C,
                                                int M, int N, int K)
{
    __shared__ __align__(16) float As[128 * GA_LD];
    __shared__ __align__(16) float Bs[32 * GB_LD];

    const int tid  = threadIdx.x;
    const int warp = tid >> 5;
    const int lane = tid & 31;
    const int q4   = lane >> 2;
    const int l4   = lane & 3;
    const int wm   = (warp >> 1) * 32;
    const int wn   = (warp & 1) * 64;
    const int bm0  = blockIdx.y * 128;
    const int bn0  = blockIdx.x * 128;

    const int a_row  = tid >> 3;
    const int a_col4 = (tid & 7) * 4;
    const int b_row  = tid >> 5;
    const int b_col4 = (tid & 31) * 4;

    const float* Abase = A + (size_t)(bm0 + a_row) * K + a_col4;
    const float* Bbase = B + (size_t)b_row * N + bn0 + b_col4;

    float acc[2][8][4];
#pragma unroll
    for (int mf = 0; mf < 2; mf++)
#pragma unroll
        for (int nf = 0; nf < 8; nf++)
#pragma unroll
            for (int c = 0; c < 4; c++) acc[mf][nf][c] = 0.0f;

    const int NT = K / 32;
    float4 ar[4], br[4];

#pragma unroll
    for (int e = 0; e < 4; e++) {
        ar[e] = *(const float4*)(Abase + (size_t)(e * 32) * K);
        br[e] = *(const float4*)(Bbase + (size_t)(e * 8) * N);
    }

    for (int kt = 0; kt < NT; kt++) {
#pragma unroll
        for (int e = 0; e < 4; e++) {
            float* ad = &As[(a_row + e * 32) * GA_LD + a_col4];
            ad[0] = to_tf32(ar[e].x); ad[1] = to_tf32(ar[e].y);
            ad[2] = to_tf32(ar[e].z); ad[3] = to_tf32(ar[e].w);
            float* bd = &Bs[(b_row + e * 8) * GB_LD + b_col4];
            bd[0] = to_tf32(br[e].x); bd[1] = to_tf32(br[e].y);
            bd[2] = to_tf32(br[e].z); bd[3] = to_tf32(br[e].w);
        }
        __syncthreads();

        if (kt + 1 < NT) {
            const float* An = Abase + (kt + 1) * 32;
            const float* Bn = Bbase + (size_t)((kt + 1) * 32) * N;
#pragma unroll
            for (int e = 0; e < 4; e++) {
                ar[e] = *(const float4*)(An + (size_t)(e * 32) * K);
                br[e] = *(const float4*)(Bn + (size_t)(e * 8) * N);
            }
        }

#pragma unroll
        for (int kk = 0; kk < 4; kk++) {
            unsigned a[2][4];
#pragma unroll
            for (int mf = 0; mf < 2; mf++) {
                int r = wm + mf * 16 + q4;
                int c0 = kk * 8 + l4;
                a[mf][0] = __float_as_uint(As[(r    ) * GA_LD + c0    ]);
                a[mf][1] = __float_as_uint(As[(r + 8) * GA_LD + c0    ]);
                a[mf][2] = __float_as_uint(As[(r    ) * GA_LD + c0 + 4]);
                a[mf][3] = __float_as_uint(As[(r + 8) * GA_LD + c0 + 4]);
            }
#pragma unroll
            for (int nf = 0; nf < 8; nf++) {
                int n = wn + nf * 8 + q4;
                unsigned b0 = __float_as_uint(Bs[(kk * 8 + l4    ) * GB_LD + n]);
                unsigned b1 = __float_as_uint(Bs[(kk * 8 + l4 + 4) * GB_LD + n]);
                mma_tf32(acc[0][nf], a[0], b0, b1);
                mma_tf32(acc[1][nf], a[1], b0, b1);
            }
        }
        __syncthreads();
    }

#pragma unroll
    for (int mf = 0; mf < 2; mf++) {
        int r = bm0 + wm + mf * 16 + q4;
#pragma unroll
        for (int nf = 0; nf < 8; nf++) {
            int cidx = bn0 + wn + nf * 8 + 2 * l4;
            float v0 = acc[mf][nf][0], v1 = acc[mf][nf][1];
            float v2 = acc[mf][nf][2], v3 = acc[mf][nf][3];
            if (RND) {
                v0 = to_tf32(v0); v1 = to_tf32(v1);
                v2 = to_tf32(v2); v3 = to_tf32(v3);
            }
            float2 lo = {v0, v1};
            float2 hi = {v2, v3};
            *(float2*)(C + (size_t)r * N + cidx)       = lo;
            *(float2*)(C + (size_t)(r + 8) * N + cidx) = hi;
        }
    }
}

// ---------------------------------------------------------------------------
// Tensor-core flash attention v4: inputs (gQ/gKV) are pre-rounded tf32, so
// the hot loop has NO cvts for Q/K/V fragments — plain LDS + bit reinterpret.
// 128 queries/CTA, 4 warps x 32 queries, cp.async double-buffered K/V,
// bitpacked mask. Grid: (SEQN/128, NHEADS, BATCH), 128 threads.
// ---------------------------------------------------------------------------
__global__ __launch_bounds__(128) void attn_tc(const float* __restrict__ Qm,
                                               const float* __restrict__ KVm,
                                               const uint32_t* __restrict__ bmask,
                                               float* __restrict__ Om)
{
    extern __shared__ __align__(16) float smem[];
    float* Ks = smem;                         // 2 x 64 x KS_LD
    float* Vs = smem + 2 * 64 * KS_LD;        // 2 x 64 x VS_LD

    const int tid  = threadIdx.x;
    const int warp = tid >> 5;
    const int lane = tid & 31;
    const int q4   = lane >> 2;
    const int l4   = lane & 3;
    const int n0   = blockIdx.x * 128;
    const int h    = blockIdx.y;
    const int b    = blockIdx.z;
    const int r0   = warp * 32;

    const float* Qbase  = Qm  + ((size_t)b * SEQN) * DIMC       + h * HD;
    const float* KVbase = KVm + ((size_t)b * SEQM) * (2 * DIMC) + h * HD;

    // ---- stage Q (pre-rounded tf32) into the Ks double-buffer region ----
#pragma unroll
    for (int e = 0; e < 16; e++) {
        int i4 = tid + e * 128;
        int i  = i4 >> 4;
        int c4 = (i4 & 15) << 2;
        float4 v = *(const float4*)(Qbase + (size_t)(n0 + i) * DIMC + c4);
        *(float4*)&Ks[i * KS_LD + c4] = v;
    }
    __syncthreads();

    // ---- build Q A-fragments (no cvt needed) ----
    unsigned qa[8][2][4];
#pragma unroll
    for (int kt = 0; kt < 8; kt++) {
#pragma unroll
        for (int mf = 0; mf < 2; mf++) {
            int r = r0 + mf * 16 + q4;
            qa[kt][mf][0] = __float_as_uint(Ks[(r    ) * KS_LD + kt * 8 + l4    ]);
            qa[kt][mf][1] = __float_as_uint(Ks[(r + 8) * KS_LD + kt * 8 + l4    ]);
            qa[kt][mf][2] = __float_as_uint(Ks[(r    ) * KS_LD + kt * 8 + l4 + 4]);
            qa[kt][mf][3] = __float_as_uint(Ks[(r + 8) * KS_LD + kt * 8 + l4 + 4]);
        }
    }
    __syncthreads();

    // ---- issue tile 0 K/V loads ----
#pragma unroll
    for (int e = 0; e < 8; e++) {
        int i4 = tid + e * 128;
        int j  = i4 >> 4;
        int d4 = (i4 & 15) << 2;
        const float* row = KVbase + (size_t)j * (2 * DIMC) + d4;
        cp_async16(smem_u32(&Ks[j * KS_LD + d4]), row);
        cp_async16(smem_u32(&Vs[j * VS_LD + d4]), row + DIMC);
    }
    cp_commit();

    float oc[2][8][4];
#pragma unroll
    for (int mf = 0; mf < 2; mf++)
#pragma unroll
        for (int nt = 0; nt < 8; nt++)
#pragma unroll
            for (int c = 0; c < 4; c++) oc[mf][nt][c] = 0.0f;
    float mrun_lo[2] = {-CUDART_INF_F, -CUDART_INF_F};
    float mrun_hi[2] = {-CUDART_INF_F, -CUDART_INF_F};
    float lsum_lo[2] = {0.0f, 0.0f};
    float lsum_hi[2] = {0.0f, 0.0f};

    const uint32_t* mp[2][2];
#pragma unroll
    for (int mf = 0; mf < 2; mf++) {
        int ilo = n0 + r0 + mf * 16 + q4;
        mp[mf][0] = bmask + ((size_t)(b * SEQN + ilo    ) * (SEQM / 32));
        mp[mf][1] = bmask + ((size_t)(b * SEQN + ilo + 8) * (SEQM / 32));
    }

    const int T = SEQM / 64;
    for (int t = 0; t < T; t++) {
        const int cur = t & 1;
        if (t + 1 < T) {
            const int nxt = (t + 1) & 1;
            const float* base = KVbase + (size_t)((t + 1) * 64) * (2 * DIMC);
            float* kb = Ks + nxt * 64 * KS_LD;
            float* vb = Vs + nxt * 64 * VS_LD;
#pragma unroll
            for (int e = 0; e < 8; e++) {
                int i4 = tid + e * 128;
                int j  = i4 >> 4;
                int d4 = (i4 & 15) << 2;
                const float* row = base + (size_t)j * (2 * DIMC) + d4;
                cp_async16(smem_u32(&kb[j * KS_LD + d4]), row);
                cp_async16(smem_u32(&vb[j * VS_LD + d4]), row + DIMC);
            }
            cp_commit();
            cp_wait<1>();
        } else {
            cp_commit();
            cp_wait<0>();
        }
        __syncthreads();

        const float* kb = Ks + cur * 64 * KS_LD;
        const float* vb = Vs + cur * 64 * VS_LD;

        // ---- prefetch bitmask words ----
        uint2 mw[2][2];
#pragma unroll
        for (int mf = 0; mf < 2; mf++) {
            mw[mf][0] = *(const uint2*)(mp[mf][0] + t * 2);
            mw[mf][1] = *(const uint2*)(mp[mf][1] + t * 2);
        }

        // ---- S = Q K^T (no cvts) ----
        float sc[2][8][4];
#pragma unroll
        for (int mf = 0; mf < 2; mf++)
#pragma unroll
            for (int nt = 0; nt < 8; nt++)
#pragma unroll
                for (int c = 0; c < 4; c++) sc[mf][nt][c] = 0.0f;
#pragma unroll
        for (int kt = 0; kt < 8; kt++) {
#pragma unroll
            for (int nt = 0; nt < 8; nt++) {
                int jrow = nt * 8 + q4;
                unsigned b0 = __float_as_uint(kb[jrow * KS_LD + kt * 8 + l4    ]);
                unsigned b1 = __float_as_uint(kb[jrow * KS_LD + kt * 8 + l4 + 4]);
                mma_tf32(sc[0][nt], qa[kt][0], b0, b1);
                mma_tf32(sc[1][nt], qa[kt][1], b0, b1);
            }
        }

        // ---- scale + mask (bit test) ----
#pragma unroll
        for (int mf = 0; mf < 2; mf++) {
#pragma unroll
            for (int nt = 0; nt < 8; nt++) {
                uint32_t wlo = (nt < 4) ? mw[mf][0].x : mw[mf][0].y;
                uint32_t whi = (nt < 4) ? mw[mf][1].x : mw[mf][1].y;
                int bit = (nt * 8 + 2 * l4) & 31;
                sc[mf][nt][0] = ((wlo >> bit) & 1u)       ? sc[mf][nt][0] * ATT_SCALE : -CUDART_INF_F;
                sc[mf][nt][1] = ((wlo >> (bit + 1)) & 1u) ? sc[mf][nt][1] * ATT_SCALE : -CUDART_INF_F;
                sc[mf][nt][2] = ((whi >> bit) & 1u)       ? sc[mf][nt][2] * ATT_SCALE : -CUDART_INF_F;
                sc[mf][nt][3] = ((whi >> (bit + 1)) & 1u) ? sc[mf][nt][3] * ATT_SCALE : -CUDART_INF_F;
            }
        }

        // ---- online softmax ----
#pragma unroll
        for (int mf = 0; mf < 2; mf++) {
            float tml = -CUDART_INF_F, tmh = -CUDART_INF_F;
#pragma unroll
            for (int nt = 0; nt < 8; nt++) {
                tml = fmaxf(tml, fmaxf(sc[mf][nt][0], sc[mf][nt][1]));
                tmh = fmaxf(tmh, fmaxf(sc[mf][nt][2], sc[mf][nt][3]));
            }
            tml = fmaxf(tml, __shfl_xor_sync(0xffffffffu, tml, 1));
            tml = fmaxf(tml, __shfl_xor_sync(0xffffffffu, tml, 2));
            tmh = fmaxf(tmh, __shfl_xor_sync(0xffffffffu, tmh, 1));
            tmh = fmaxf(tmh, __shfl_xor_sync(0xffffffffu, tmh, 2));

            float mnew_lo = fmaxf(mrun_lo[mf], tml);
            float mnew_hi = fmaxf(mrun_hi[mf], tmh);
            bool  inf_lo  = (mnew_lo == -CUDART_INF_F);
            bool  inf_hi  = (mnew_hi == -CUDART_INF_F);

            float ssl = 0.0f, ssh = 0.0f;
#pragma unroll
            for (int nt = 0; nt < 8; nt++) {
                float p0 = inf_lo ? 0.0f : __expf(sc[mf][nt][0] - mnew_lo);
                float p1 = inf_lo ? 0.0f : __expf(sc[mf][nt][1] - mnew_lo);
                float p2 = inf_hi ? 0.0f : __expf(sc[mf][nt][2] - mnew_hi);
                float p3 = inf_hi ? 0.0f : __expf(sc[mf][nt][3] - mnew_hi);
                sc[mf][nt][0] = p0; sc[mf][nt][1] = p1;
                sc[mf][nt][2] = p2; sc[mf][nt][3] = p3;
                ssl += p0 + p1;
                ssh += p2 + p3;
            }
            ssl += __shfl_xor_sync(0xffffffffu, ssl, 1);
            ssl += __shfl_xor_sync(0xffffffffu, ssl, 2);
            ssh += __shfl_xor_sync(0xffffffffu, ssh, 1);
            ssh += __shfl_xor_sync(0xffffffffu, ssh, 2);

            float alpha_lo = (mrun_lo[mf] == -CUDART_INF_F) ? 0.0f : __expf(mrun_lo[mf] - mnew_lo);
            float alpha_hi = (mrun_hi[mf] == -CUDART_INF_F) ? 0.0f : __expf(mrun_hi[mf] - mnew_hi);
            lsum_lo[mf] = lsum_lo[mf] * alpha_lo + ssl;
            lsum_hi[mf] = lsum_hi[mf] * alpha_hi + ssh;
            mrun_lo[mf] = mnew_lo;
            mrun_hi[mf] = mnew_hi;
#pragma unroll
            for (int nt = 0; nt < 8; nt++) {
                oc[mf][nt][0] *= alpha_lo; oc[mf][nt][1] *= alpha_lo;
                oc[mf][nt][2] *= alpha_hi; oc[mf][nt][3] *= alpha_hi;
            }
        }

        // ---- O += P @ V (P cvt'd once; V needs no cvt) ----
        const int base2 = lane & ~3;
        const int src  = base2 | (l4 >> 1);
        const int src2 = src + 2;
        const bool odd = lane & 1;
#pragma unroll
        for (int kt = 0; kt < 8; kt++) {
            unsigned pa[2][4];
#pragma unroll
            for (int mf = 0; mf < 2; mf++) {
                float c0 = sc[mf][kt][0], c1 = sc[mf][kt][1];
                float c2 = sc[mf][kt][2], c3 = sc[mf][kt][3];
                float t00 = __shfl_sync(0xffffffffu, c0, src);
                float t01 = __shfl_sync(0xffffffffu, c1, src);
                float t10 = __shfl_sync(0xffffffffu, c2, src);
                float t11 = __shfl_sync(0xffffffffu, c3, src);
                float t20 = __shfl_sync(0xffffffffu, c0, src2);
                float t21 = __shfl_sync(0xffffffffu, c1, src2);
                float t30 = __shfl_sync(0xffffffffu, c2, src2);
                float t31 = __shfl_sync(0xffffffffu, c3, src2);
                pa[mf][0] = tf32_bits(odd ? t01 : t00);
                pa[mf][1] = tf32_bits(odd ? t11 : t10);
                pa[mf][2] = tf32_bits(odd ? t21 : t20);
                pa[mf][3] = tf32_bits(odd ? t31 : t30);
            }
#pragma unroll
            for (int nt = 0; nt < 8; nt++) {
                int vrow = kt * 8 + l4;
                unsigned b0 = __float_as_uint(vb[(vrow    ) * VS_LD + nt * 8 + q4]);
                unsigned b1 = __float_as_uint(vb[(vrow + 4) * VS_LD + nt * 8 + q4]);
                mma_tf32(oc[0][nt], pa[0], b0, b1);
                mma_tf32(oc[1][nt], pa[1], b0, b1);
            }
        }
        __syncthreads();
    }

    // ---- normalize + write O ----
#pragma unroll
    for (int mf = 0; mf < 2; mf++) {
        float inv_lo = 1.0f / lsum_lo[mf];
        float inv_hi = 1.0f / lsum_hi[mf];
        int ilo = n0 + r0 + mf * 16 + q4;
        float* orow0 = Om + (size_t)(b * SEQN + ilo    ) * DIMC + h * HD;
        float* orow1 = Om + (size_t)(b * SEQN + ilo + 8) * DIMC + h * HD;
#pragma unroll
        for (int nt = 0; nt < 8; nt++) {
            int d0 = nt * 8 + 2 * l4;
            float2 lo = {oc[mf][nt][0] * inv_lo, oc[mf][nt][1] * inv_lo};
            float2 hi = {oc[mf][nt][2] * inv_hi, oc[mf][nt][3] * inv_hi};
            *(float2*)(orow0 + d0) = lo;
            *(float2*)(orow1 + d0) = hi;
        }
    }
}

// ---------------------------------------------------------------------------
extern "C" void kernel_launch(void* const* d_in, const int* in_sizes, int n_in,
                              void* d_out, int out_size)
{
    const float* x    = (const float*)d_in[0];
    const float* ctx  = (const float*)d_in[1];
    const int*   mask = (const int*)d_in[2];
    const float* Wq   = (const float*)d_in[3];
    const float* Wkv  = (const float*)d_in[4];
    const float* Wo   = (const float*)d_in[5];
    float*       out  = (float*)d_out;

    float *gQ, *gKV, *gO;
    uint32_t* gM;
    cudaGetSymbolAddress((void**)&gQ,  g_Q);
    cudaGetSymbolAddress((void**)&gKV, g_KV);
    cudaGetSymbolAddress((void**)&gO,  g_O);
    cudaGetSymbolAddress((void**)&gM,  g_mask);

    cudaFuncSetAttribute(attn_tc, cudaFuncAttributeMaxDynamicSharedMemorySize,
                         ATTN_SMEM_BYTES);

    const int Mrows = BATCH * SEQN;   // 8192
    const int mask_n = BATCH * SEQN * SEQM;

    pack_mask<<<mask_n / 256, 256>>>(mask, gM, mask_n);
    // Q/KV projections: outputs pre-rounded to tf32 (consumed by attention MMA)
    tgemm128<true><<<dim3(DIMC / 128, Mrows / 128), 256>>>(x, Wq, gQ, Mrows, DIMC, DIMC);
    tgemm128<true><<<dim3(2 * DIMC / 128, Mrows / 128), 256>>>(ctx, Wkv, gKV, Mrows, 2 * DIMC, DIMC);
    attn_tc<<<dim3(SEQN / 128, NHEADS, BATCH), 128, ATTN_SMEM_BYTES>>>(gQ, gKV, gM, gO);
    // O projection: exact fp32 output
    tgemm128<false><<<dim3(DIMC / 128, Mrows / 128), 256>>>(gO, Wo, out, Mrows, DIMC, DIMC);
}

// round 10
// speedup vs baseline: 3.7689x; 1.0238x over previous
#include <cuda_runtime.h>
#include <math_constants.h>
#include <cstddef>
#include <cstdint>

#define DIMC   512
#define HD     64
#define NHEADS 8
#define BATCH  4
#define SEQN   2048
#define SEQM   2048
#define ATT_SCALE 0.125f   // 64^-0.5 (power of two: exact fold into Q)

#define KS_LD 68   // attention K smem stride (floats)
#define VS_LD 72   // attention V smem stride (floats)

#define GA_LD 36   // gemm A smem stride
#define GB_LD 136  // gemm B smem stride

#define ATTN_SMEM_BYTES ((2 * 64 * KS_LD + 2 * 64 * VS_LD) * 4)
#define MASK_WORDS (BATCH * SEQN * (SEQM / 32))

// ---------------- scratch (device globals: allocation-free) ----------------
__device__ float    g_Q   [BATCH * SEQN * DIMC];       // 16 MB (tf32-rounded)
__device__ float    g_KV  [BATCH * SEQM * 2 * DIMC];   // 32 MB (tf32-rounded)
__device__ float    g_O   [BATCH * SEQN * DIMC];       // 16 MB
__device__ uint32_t g_mask[MASK_WORDS];                // 2 MB bitpacked mask

// ---------------------------------------------------------------------------
// tf32 / async helpers
// ---------------------------------------------------------------------------
__device__ __forceinline__ float to_tf32(float x) {
    unsigned u;
    asm("cvt.rna.tf32.f32 %0, %1;" : "=r"(u) : "f"(x));
    return __uint_as_float(u);
}
__device__ __forceinline__ unsigned tf32_bits(float x) {
    unsigned u;
    asm("cvt.rna.tf32.f32 %0, %1;" : "=r"(u) : "f"(x));
    return u;
}
__device__ __forceinline__ void mma_tf32(float c[4], const unsigned a[4],
                                         unsigned b0, unsigned b1)
{
    asm volatile(
        "mma.sync.aligned.m16n8k8.row.col.f32.tf32.tf32.f32 "
        "{%0,%1,%2,%3},{%4,%5,%6,%7},{%8,%9},{%0,%1,%2,%3};"
        : "+f"(c[0]), "+f"(c[1]), "+f"(c[2]), "+f"(c[3])
        : "r"(a[0]), "r"(a[1]), "r"(a[2]), "r"(a[3]), "r"(b0), "r"(b1));
}
__device__ __forceinline__ void cp_async16(uint32_t smem_addr, const void* gptr) {
    asm volatile("cp.async.cg.shared.global [%0], [%1], 16;"
                 :: "r"(smem_addr), "l"(gptr));
}
__device__ __forceinline__ void cp_commit() {
    asm volatile("cp.async.commit_group;");
}
template <int N>
__device__ __forceinline__ void cp_wait() {
    asm volatile("cp.async.wait_group %0;" :: "n"(N));
}
__device__ __forceinline__ uint32_t smem_u32(const void* p) {
    return (uint32_t)__cvta_generic_to_shared(p);
}

// ---------------------------------------------------------------------------
// Mask bit-pack: 32 int32 -> 1 uint32 via ballot.
// ---------------------------------------------------------------------------
__global__ __launch_bounds__(256) void pack_mask(const int* __restrict__ mask,
                                                 uint32_t* __restrict__ bm, int n)
{
    int idx = blockIdx.x * blockDim.x + threadIdx.x;
    if (idx < n) {
        unsigned bal = __ballot_sync(0xffffffffu, mask[idx] != 0);
        if ((threadIdx.x & 31) == 0) bm[idx >> 5] = bal;
    }
}

// ---------------------------------------------------------------------------
// tf32 tensor-core GEMM (unchanged, passing): C = A @ B.
// RND: round outputs to tf32 for tensors consumed by attention MMAs.
// ---------------------------------------------------------------------------
template <bool RND>
__global__ __launch_bounds__(256) void tgemm128(const float* __restrict__ A,
                                                const float* __restrict__ B,
                                                float* __restrict__ C,
                                                int M, int N, int K)
{
    __shared__ __align__(16) float As[128 * GA_LD];
    __shared__ __align__(16) float Bs[32 * GB_LD];

    const int tid  = threadIdx.x;
    const int warp = tid >> 5;
    const int lane = tid & 31;
    const int q4   = lane >> 2;
    const int l4   = lane & 3;
    const int wm   = (warp >> 1) * 32;
    const int wn   = (warp & 1) * 64;
    const int bm0  = blockIdx.y * 128;
    const int bn0  = blockIdx.x * 128;

    const int a_row  = tid >> 3;
    const int a_col4 = (tid & 7) * 4;
    const int b_row  = tid >> 5;
    const int b_col4 = (tid & 31) * 4;

    const float* Abase = A + (size_t)(bm0 + a_row) * K + a_col4;
    const float* Bbase = B + (size_t)b_row * N + bn0 + b_col4;

    float acc[2][8][4];
#pragma unroll
    for (int mf = 0; mf < 2; mf++)
#pragma unroll
        for (int nf = 0; nf < 8; nf++)
#pragma unroll
            for (int c = 0; c < 4; c++) acc[mf][nf][c] = 0.0f;

    const int NT = K / 32;
    float4 ar[4], br[4];

#pragma unroll
    for (int e = 0; e < 4; e++) {
        ar[e] = *(const float4*)(Abase + (size_t)(e * 32) * K);
        br[e] = *(const float4*)(Bbase + (size_t)(e * 8) * N);
    }

    for (int kt = 0; kt < NT; kt++) {
#pragma unroll
        for (int e = 0; e < 4; e++) {
            float* ad = &As[(a_row + e * 32) * GA_LD + a_col4];
            ad[0] = to_tf32(ar[e].x); ad[1] = to_tf32(ar[e].y);
            ad[2] = to_tf32(ar[e].z); ad[3] = to_tf32(ar[e].w);
            float* bd = &Bs[(b_row + e * 8) * GB_LD + b_col4];
            bd[0] = to_tf32(br[e].x); bd[1] = to_tf32(br[e].y);
            bd[2] = to_tf32(br[e].z); bd[3] = to_tf32(br[e].w);
        }
        __syncthreads();

        if (kt + 1 < NT) {
            const float* An = Abase + (kt + 1) * 32;
            const float* Bn = Bbase + (size_t)((kt + 1) * 32) * N;
#pragma unroll
            for (int e = 0; e < 4; e++) {
                ar[e] = *(const float4*)(An + (size_t)(e * 32) * K);
                br[e] = *(const float4*)(Bn + (size_t)(e * 8) * N);
            }
        }

#pragma unroll
        for (int kk = 0; kk < 4; kk++) {
            unsigned a[2][4];
#pragma unroll
            for (int mf = 0; mf < 2; mf++) {
                int r = wm + mf * 16 + q4;
                int c0 = kk * 8 + l4;
                a[mf][0] = __float_as_uint(As[(r    ) * GA_LD + c0    ]);
                a[mf][1] = __float_as_uint(As[(r + 8) * GA_LD + c0    ]);
                a[mf][2] = __float_as_uint(As[(r    ) * GA_LD + c0 + 4]);
                a[mf][3] = __float_as_uint(As[(r + 8) * GA_LD + c0 + 4]);
            }
#pragma unroll
            for (int nf = 0; nf < 8; nf++) {
                int n = wn + nf * 8 + q4;
                unsigned b0 = __float_as_uint(Bs[(kk * 8 + l4    ) * GB_LD + n]);
                unsigned b1 = __float_as_uint(Bs[(kk * 8 + l4 + 4) * GB_LD + n]);
                mma_tf32(acc[0][nf], a[0], b0, b1);
                mma_tf32(acc[1][nf], a[1], b0, b1);
            }
        }
        __syncthreads();
    }

#pragma unroll
    for (int mf = 0; mf < 2; mf++) {
        int r = bm0 + wm + mf * 16 + q4;
#pragma unroll
        for (int nf = 0; nf < 8; nf++) {
            int cidx = bn0 + wn + nf * 8 + 2 * l4;
            float v0 = acc[mf][nf][0], v1 = acc[mf][nf][1];
            float v2 = acc[mf][nf][2], v3 = acc[mf][nf][3];
            if (RND) {
                v0 = to_tf32(v0); v1 = to_tf32(v1);
                v2 = to_tf32(v2); v3 = to_tf32(v3);
            }
            float2 lo = {v0, v1};
            float2 hi = {v2, v3};
            *(float2*)(C + (size_t)r * N + cidx)       = lo;
            *(float2*)(C + (size_t)(r + 8) * N + cidx) = hi;
        }
    }
}

// ---------------------------------------------------------------------------
// Tensor-core flash attention v5:
//  - 256 threads (8 warps), 16 queries/warp -> 128 queries/CTA.
//    Low register footprint (qa/oc/sc = 32 regs each) + launch_bounds(256,2)
//    -> 16 warps/SM, no spills.
//  - cp.async double-buffered K/V; pre-rounded tf32 inputs (no cvts in loop).
//  - ATT_SCALE folded into Q fragments (x2^-3, exact).
//  - bitpacked mask with all-ones fast path.
// Grid: (SEQN/128, NHEADS, BATCH).
// ---------------------------------------------------------------------------
__global__ __launch_bounds__(256, 2) void attn_tc(const float* __restrict__ Qm,
                                                  const float* __restrict__ KVm,
                                                  const uint32_t* __restrict__ bmask,
                                                  float* __restrict__ Om)
{
    extern __shared__ __align__(16) float smem[];
    float* Ks = smem;                         // 2 x 64 x KS_LD (= 128 x KS_LD)
    float* Vs = smem + 2 * 64 * KS_LD;        // 2 x 64 x VS_LD

    const int tid  = threadIdx.x;
    const int warp = tid >> 5;
    const int lane = tid & 31;
    const int q4   = lane >> 2;
    const int l4   = lane & 3;
    const int n0   = blockIdx.x * 128;
    const int h    = blockIdx.y;
    const int b    = blockIdx.z;
    const int r0   = warp * 16;               // warp's first query row (of 128)

    const float* Qbase  = Qm  + ((size_t)b * SEQN) * DIMC       + h * HD;
    const float* KVbase = KVm + ((size_t)b * SEQM) * (2 * DIMC) + h * HD;

    // ---- stage Q (pre-rounded tf32, 128 rows x 64) into Ks region ----
#pragma unroll
    for (int e = 0; e < 8; e++) {
        int i4 = tid + e * 256;               // 0..2047 float4s
        int i  = i4 >> 4;                     // row 0..127
        int c4 = (i4 & 15) << 2;
        float4 v = *(const float4*)(Qbase + (size_t)(n0 + i) * DIMC + c4);
        *(float4*)&Ks[i * KS_LD + c4] = v;
    }
    __syncthreads();

    // ---- build Q A-fragments with ATT_SCALE folded in (exact x2^-3) ----
    unsigned qa[8][4];
#pragma unroll
    for (int kt = 0; kt < 8; kt++) {
        int r = r0 + q4;
        qa[kt][0] = __float_as_uint(ATT_SCALE * Ks[(r    ) * KS_LD + kt * 8 + l4    ]);
        qa[kt][1] = __float_as_uint(ATT_SCALE * Ks[(r + 8) * KS_LD + kt * 8 + l4    ]);
        qa[kt][2] = __float_as_uint(ATT_SCALE * Ks[(r    ) * KS_LD + kt * 8 + l4 + 4]);
        qa[kt][3] = __float_as_uint(ATT_SCALE * Ks[(r + 8) * KS_LD + kt * 8 + l4 + 4]);
    }
    __syncthreads();   // Q reads done; Ks region reusable for K tiles

    // ---- issue tile 0 K/V loads ----
#pragma unroll
    for (int e = 0; e < 4; e++) {
        int i4 = tid + e * 256;
        int j  = i4 >> 4;
        int d4 = (i4 & 15) << 2;
        const float* row = KVbase + (size_t)j * (2 * DIMC) + d4;
        cp_async16(smem_u32(&Ks[j * KS_LD + d4]), row);
        cp_async16(smem_u32(&Vs[j * VS_LD + d4]), row + DIMC);
    }
    cp_commit();

    float oc[8][4];
#pragma unroll
    for (int nt = 0; nt < 8; nt++)
#pragma unroll
        for (int c = 0; c < 4; c++) oc[nt][c] = 0.0f;
    float mrun_lo = -CUDART_INF_F, mrun_hi = -CUDART_INF_F;
    float lsum_lo = 0.0f, lsum_hi = 0.0f;

    const int i0 = n0 + r0 + q4;
    const int i1 = i0 + 8;
    const uint32_t* mp0 = bmask + ((size_t)(b * SEQN + i0) * (SEQM / 32));
    const uint32_t* mp1 = bmask + ((size_t)(b * SEQN + i1) * (SEQM / 32));

    const int T = SEQM / 64;
    for (int t = 0; t < T; t++) {
        const int cur = t & 1;
        if (t + 1 < T) {
            const int nxt = (t + 1) & 1;
            const float* base = KVbase + (size_t)((t + 1) * 64) * (2 * DIMC);
            float* kb = Ks + nxt * 64 * KS_LD;
            float* vb = Vs + nxt * 64 * VS_LD;
#pragma unroll
            for (int e = 0; e < 4; e++) {
                int i4 = tid + e * 256;
                int j  = i4 >> 4;
                int d4 = (i4 & 15) << 2;
                const float* row = base + (size_t)j * (2 * DIMC) + d4;
                cp_async16(smem_u32(&kb[j * KS_LD + d4]), row);
                cp_async16(smem_u32(&vb[j * VS_LD + d4]), row + DIMC);
            }
            cp_commit();
            cp_wait<1>();
        } else {
            cp_commit();
            cp_wait<0>();
        }
        __syncthreads();

        const float* kb = Ks + cur * 64 * KS_LD;
        const float* vb = Vs + cur * 64 * VS_LD;

        // ---- prefetch bitmask words (overlap QK MMAs) ----
        uint2 mw0 = *(const uint2*)(mp0 + t * 2);
        uint2 mw1 = *(const uint2*)(mp1 + t * 2);

        // ---- S = (Q*scale) K^T ----
        float sc[8][4];
#pragma unroll
        for (int nt = 0; nt < 8; nt++)
#pragma unroll
            for (int c = 0; c < 4; c++) sc[nt][c] = 0.0f;
#pragma unroll
        for (int kt = 0; kt < 8; kt++) {
#pragma unroll
            for (int nt = 0; nt < 8; nt++) {
                int jrow = nt * 8 + q4;
                unsigned b0 = __float_as_uint(kb[jrow * KS_LD + kt * 8 + l4    ]);
                unsigned b1 = __float_as_uint(kb[jrow * KS_LD + kt * 8 + l4 + 4]);
                mma_tf32(sc[nt], qa[kt], b0, b1);
            }
        }

        // ---- mask (all-ones fast path; bit test otherwise) ----
        if ((mw0.x & mw0.y & mw1.x & mw1.y) != 0xffffffffu) {
#pragma unroll
            for (int nt = 0; nt < 8; nt++) {
                uint32_t wlo = (nt < 4) ? mw0.x : mw0.y;
                uint32_t whi = (nt < 4) ? mw1.x : mw1.y;
                int bit = (nt * 8 + 2 * l4) & 31;
                if (!((wlo >> bit) & 1u))       sc[nt][0] = -CUDART_INF_F;
                if (!((wlo >> (bit + 1)) & 1u)) sc[nt][1] = -CUDART_INF_F;
                if (!((whi >> bit) & 1u))       sc[nt][2] = -CUDART_INF_F;
                if (!((whi >> (bit + 1)) & 1u)) sc[nt][3] = -CUDART_INF_F;
            }
        }

        // ---- online softmax (rows shared by 4 lanes) ----
        float tml = -CUDART_INF_F, tmh = -CUDART_INF_F;
#pragma unroll
        for (int nt = 0; nt < 8; nt++) {
            tml = fmaxf(tml, fmaxf(sc[nt][0], sc[nt][1]));
            tmh = fmaxf(tmh, fmaxf(sc[nt][2], sc[nt][3]));
        }
        tml = fmaxf(tml, __shfl_xor_sync(0xffffffffu, tml, 1));
        tml = fmaxf(tml, __shfl_xor_sync(0xffffffffu, tml, 2));
        tmh = fmaxf(tmh, __shfl_xor_sync(0xffffffffu, tmh, 1));
        tmh = fmaxf(tmh, __shfl_xor_sync(0xffffffffu, tmh, 2));

        float mnew_lo = fmaxf(mrun_lo, tml);
        float mnew_hi = fmaxf(mrun_hi, tmh);
        bool  inf_lo  = (mnew_lo == -CUDART_INF_F);
        bool  inf_hi  = (mnew_hi == -CUDART_INF_F);

        float ssl = 0.0f, ssh = 0.0f;
#pragma unroll
        for (int nt = 0; nt < 8; nt++) {
            float p0 = inf_lo ? 0.0f : __expf(sc[nt][0] - mnew_lo);
            float p1 = inf_lo ? 0.0f : __expf(sc[nt][1] - mnew_lo);
            float p2 = inf_hi ? 0.0f : __expf(sc[nt][2] - mnew_hi);
            float p3 = inf_hi ? 0.0f : __expf(sc[nt][3] - mnew_hi);
            sc[nt][0] = p0; sc[nt][1] = p1; sc[nt][2] = p2; sc[nt][3] = p3;
            ssl += p0 + p1;
            ssh += p2 + p3;
        }
        ssl += __shfl_xor_sync(0xffffffffu, ssl, 1);
        ssl += __shfl_xor_sync(0xffffffffu, ssl, 2);
        ssh += __shfl_xor_sync(0xffffffffu, ssh, 1);
        ssh += __shfl_xor_sync(0xffffffffu, ssh, 2);

        float alpha_lo = (mrun_lo == -CUDART_INF_F) ? 0.0f : __expf(mrun_lo - mnew_lo);
        float alpha_hi = (mrun_hi == -CUDART_INF_F) ? 0.0f : __expf(mrun_hi - mnew_hi);
        lsum_lo = lsum_lo * alpha_lo + ssl;
        lsum_hi = lsum_hi * alpha_hi + ssh;
        mrun_lo = mnew_lo;
        mrun_hi = mnew_hi;
#pragma unroll
        for (int nt = 0; nt < 8; nt++) {
            oc[nt][0] *= alpha_lo; oc[nt][1] *= alpha_lo;
            oc[nt][2] *= alpha_hi; oc[nt][3] *= alpha_hi;
        }

        // ---- O += P @ V (P C-frag -> A-frag via shuffles, cvt once) ----
        const int base2 = lane & ~3;
        const int src  = base2 | (l4 >> 1);
        const int src2 = src + 2;
        const bool odd = lane & 1;
#pragma unroll
        for (int kt = 0; kt < 8; kt++) {
            float c0 = sc[kt][0], c1 = sc[kt][1], c2 = sc[kt][2], c3 = sc[kt][3];
            float t00 = __shfl_sync(0xffffffffu, c0, src);
            float t01 = __shfl_sync(0xffffffffu, c1, src);
            float t10 = __shfl_sync(0xffffffffu, c2, src);
            float t11 = __shfl_sync(0xffffffffu, c3, src);
            float t20 = __shfl_sync(0xffffffffu, c0, src2);
            float t21 = __shfl_sync(0xffffffffu, c1, src2);
            float t30 = __shfl_sync(0xffffffffu, c2, src2);
            float t31 = __shfl_sync(0xffffffffu, c3, src2);
            unsigned pa[4];
            pa[0] = tf32_bits(odd ? t01 : t00);
            pa[1] = tf32_bits(odd ? t11 : t10);
            pa[2] = tf32_bits(odd ? t21 : t20);
            pa[3] = tf32_bits(odd ? t31 : t30);
#pragma unroll
            for (int nt = 0; nt < 8; nt++) {
                int vrow = kt * 8 + l4;
                unsigned b0 = __float_as_uint(vb[(vrow    ) * VS_LD + nt * 8 + q4]);
                unsigned b1 = __float_as_uint(vb[(vrow + 4) * VS_LD + nt * 8 + q4]);
                mma_tf32(oc[nt], pa, b0, b1);
            }
        }
        __syncthreads();
    }

    // ---- normalize + write O ----
    float inv_lo = 1.0f / lsum_lo;
    float inv_hi = 1.0f / lsum_hi;
    float* orow0 = Om + (size_t)(b * SEQN + i0) * DIMC + h * HD;
    float* orow1 = Om + (size_t)(b * SEQN + i1) * DIMC + h * HD;
#pragma unroll
    for (int nt = 0; nt < 8; nt++) {
        int d0 = nt * 8 + 2 * l4;
        float2 lo = {oc[nt][0] * inv_lo, oc[nt][1] * inv_lo};
        float2 hi = {oc[nt][2] * inv_hi, oc[nt][3] * inv_hi};
        *(float2*)(orow0 + d0) = lo;
        *(float2*)(orow1 + d0) = hi;
    }
}

// ---------------------------------------------------------------------------
extern "C" void kernel_launch(void* const* d_in, const int* in_sizes, int n_in,
                              void* d_out, int out_size)
{
    const float* x    = (const float*)d_in[0];
    const float* ctx  = (const float*)d_in[1];
    const int*   mask = (const int*)d_in[2];
    const float* Wq   = (const float*)d_in[3];
    const float* Wkv  = (const float*)d_in[4];
    const float* Wo   = (const float*)d_in[5];
    float*       out  = (float*)d_out;

    float *gQ, *gKV, *gO;
    uint32_t* gM;
    cudaGetSymbolAddress((void**)&gQ,  g_Q);
    cudaGetSymbolAddress((void**)&gKV, g_KV);
    cudaGetSymbolAddress((void**)&gO,  g_O);
    cudaGetSymbolAddress((void**)&gM,  g_mask);

    cudaFuncSetAttribute(attn_tc, cudaFuncAttributeMaxDynamicSharedMemorySize,
                         ATTN_SMEM_BYTES);

    const int Mrows = BATCH * SEQN;   // 8192
    const int mask_n = BATCH * SEQN * SEQM;

    pack_mask<<<mask_n / 256, 256>>>(mask, gM, mask_n);
    tgemm128<true><<<dim3(DIMC / 128, Mrows / 128), 256>>>(x, Wq, gQ, Mrows, DIMC, DIMC);
    tgemm128<true><<<dim3(2 * DIMC / 128, Mrows / 128), 256>>>(ctx, Wkv, gKV, Mrows, 2 * DIMC, DIMC);
    attn_tc<<<dim3(SEQN / 128, NHEADS, BATCH), 256, ATTN_SMEM_BYTES>>>(gQ, gKV, gM, gO);
    tgemm128<false><<<dim3(DIMC / 128, Mrows / 128), 256>>>(gO, Wo, out, Mrows, DIMC, DIMC);
}

// round 11
// speedup vs baseline: 3.8718x; 1.0273x over previous
#include <cuda_runtime.h>
#include <math_constants.h>
#include <cstddef>
#include <cstdint>

#define DIMC   512
#define HD     64
#define NHEADS 8
#define BATCH  4
#define SEQN   2048
#define SEQM   2048
#define ATT_SCALE 0.125f   // 64^-0.5 (power of two: exact fold into Q)

#define KS_LD 68   // attention K smem stride (floats)
#define VS_LD 72   // attention V smem stride (floats)

#define GA_LD 36   // gemm A smem stride (128 rows x 32 cols + pad)
#define GB_LD 136  // gemm B smem stride (32 rows x 128 cols + pad)
#define NSTAGE 3   // gemm cp.async pipeline depth

#define ATTN_SMEM_BYTES ((2 * 64 * KS_LD + 2 * 64 * VS_LD) * 4)
#define TG_SMEM_BYTES   ((NSTAGE * 128 * GA_LD + NSTAGE * 32 * GB_LD) * 4)
#define MASK_WORDS (BATCH * SEQN * (SEQM / 32))

// ---------------- scratch (device globals: allocation-free) ----------------
__device__ float    g_Q   [BATCH * SEQN * DIMC];       // 16 MB (tf32-rounded)
__device__ float    g_KV  [BATCH * SEQM * 2 * DIMC];   // 32 MB (tf32-rounded)
__device__ float    g_O   [BATCH * SEQN * DIMC];       // 16 MB
__device__ uint32_t g_mask[MASK_WORDS];                // 2 MB bitpacked mask

// ---------------------------------------------------------------------------
// tf32 / async helpers
// ---------------------------------------------------------------------------
__device__ __forceinline__ float to_tf32(float x) {
    unsigned u;
    asm("cvt.rna.tf32.f32 %0, %1;" : "=r"(u) : "f"(x));
    return __uint_as_float(u);
}
__device__ __forceinline__ unsigned tf32_bits(float x) {
    unsigned u;
    asm("cvt.rna.tf32.f32 %0, %1;" : "=r"(u) : "f"(x));
    return u;
}
__device__ __forceinline__ void mma_tf32(float c[4], const unsigned a[4],
                                         unsigned b0, unsigned b1)
{
    asm volatile(
        "mma.sync.aligned.m16n8k8.row.col.f32.tf32.tf32.f32 "
        "{%0,%1,%2,%3},{%4,%5,%6,%7},{%8,%9},{%0,%1,%2,%3};"
        : "+f"(c[0]), "+f"(c[1]), "+f"(c[2]), "+f"(c[3])
        : "r"(a[0]), "r"(a[1]), "r"(a[2]), "r"(a[3]), "r"(b0), "r"(b1));
}
__device__ __forceinline__ void cp_async16(uint32_t smem_addr, const void* gptr) {
    asm volatile("cp.async.cg.shared.global [%0], [%1], 16;"
                 :: "r"(smem_addr), "l"(gptr));
}
__device__ __forceinline__ void cp_commit() {
    asm volatile("cp.async.commit_group;");
}
template <int N>
__device__ __forceinline__ void cp_wait() {
    asm volatile("cp.async.wait_group %0;" :: "n"(N));
}
__device__ __forceinline__ uint32_t smem_u32(const void* p) {
    return (uint32_t)__cvta_generic_to_shared(p);
}

// ---------------------------------------------------------------------------
// Mask bit-pack: 32 int32 -> 1 uint32 via ballot.
// ---------------------------------------------------------------------------
__global__ __launch_bounds__(256) void pack_mask(const int* __restrict__ mask,
                                                 uint32_t* __restrict__ bm, int n)
{
    int idx = blockIdx.x * blockDim.x + threadIdx.x;
    if (idx < n) {
        unsigned bal = __ballot_sync(0xffffffffu, mask[idx] != 0);
        if ((threadIdx.x & 31) == 0) bm[idx >> 5] = bal;
    }
}

// ---------------------------------------------------------------------------
// tf32 tensor-core GEMM v2: C = A @ B, 3-stage cp.async pipeline.
// Raw fp32 staged in smem; cvt.rna at fragment read (bit-identical to
// cvt-at-store). One __syncthreads per k-tile; loads issued 2 tiles ahead.
// RND: round outputs to tf32 for tensors consumed by attention MMAs.
// ---------------------------------------------------------------------------
template <bool RND>
__global__ __launch_bounds__(256) void tgemm128(const float* __restrict__ A,
                                                const float* __restrict__ B,
                                                float* __restrict__ C,
                                                int M, int N, int K)
{
    extern __shared__ __align__(16) float dsm[];
    float* As = dsm;                               // NSTAGE x 128 x GA_LD
    float* Bs = dsm + NSTAGE * 128 * GA_LD;        // NSTAGE x 32 x GB_LD

    const int tid  = threadIdx.x;
    const int warp = tid >> 5;
    const int lane = tid & 31;
    const int q4   = lane >> 2;
    const int l4   = lane & 3;
    const int wm   = (warp >> 1) * 32;
    const int wn   = (warp & 1) * 64;
    const int bm0  = blockIdx.y * 128;
    const int bn0  = blockIdx.x * 128;

    const int a_row  = tid >> 3;          // 0..31 (rows advance by 32 per e)
    const int a_col4 = (tid & 7) * 4;
    const int b_row  = tid >> 5;          // 0..7  (rows advance by 8 per e)
    const int b_col4 = (tid & 31) * 4;

    const float* Abase = A + (size_t)(bm0 + a_row) * K + a_col4;
    const float* Bbase = B + (size_t)b_row * N + bn0 + b_col4;

    const int NT = K / 32;

    // issue k-tile kt into pipeline slot kt % NSTAGE (empty group if kt >= NT)
    auto issue_tile = [&](int kt) {
        if (kt < NT) {
            int s = kt % NSTAGE;
            float* as = As + s * 128 * GA_LD;
            float* bs = Bs + s * 32 * GB_LD;
            const float* An = Abase + kt * 32;
            const float* Bn = Bbase + (size_t)(kt * 32) * N;
#pragma unroll
            for (int e = 0; e < 4; e++) {
                cp_async16(smem_u32(&as[(a_row + e * 32) * GA_LD + a_col4]),
                           An + (size_t)(e * 32) * K);
                cp_async16(smem_u32(&bs[(b_row + e * 8) * GB_LD + b_col4]),
                           Bn + (size_t)(e * 8) * N);
            }
        }
        cp_commit();
    };

    float acc[2][8][4];
#pragma unroll
    for (int mf = 0; mf < 2; mf++)
#pragma unroll
        for (int nf = 0; nf < 8; nf++)
#pragma unroll
            for (int c = 0; c < 4; c++) acc[mf][nf][c] = 0.0f;

    // prologue: tiles 0 and 1 in flight
    issue_tile(0);
    issue_tile(1);

    for (int kt = 0; kt < NT; kt++) {
        cp_wait<1>();          // group(kt) complete (group(kt+1) may fly)
        __syncthreads();       // visibility + all warps done with slot (kt-1)%3
        issue_tile(kt + 2);    // into slot (kt+2)%3 == (kt-1)%3 (now free)

        const float* as = As + (kt % NSTAGE) * 128 * GA_LD;
        const float* bs = Bs + (kt % NSTAGE) * 32 * GB_LD;

#pragma unroll
        for (int kk = 0; kk < 4; kk++) {
            unsigned a[2][4];
#pragma unroll
            for (int mf = 0; mf < 2; mf++) {
                int r = wm + mf * 16 + q4;
                int c0 = kk * 8 + l4;
                a[mf][0] = tf32_bits(as[(r    ) * GA_LD + c0    ]);
                a[mf][1] = tf32_bits(as[(r + 8) * GA_LD + c0    ]);
                a[mf][2] = tf32_bits(as[(r    ) * GA_LD + c0 + 4]);
                a[mf][3] = tf32_bits(as[(r + 8) * GA_LD + c0 + 4]);
            }
#pragma unroll
            for (int nf = 0; nf < 8; nf++) {
                int n = wn + nf * 8 + q4;
                unsigned b0 = tf32_bits(bs[(kk * 8 + l4    ) * GB_LD + n]);
                unsigned b1 = tf32_bits(bs[(kk * 8 + l4 + 4) * GB_LD + n]);
                mma_tf32(acc[0][nf], a[0], b0, b1);
                mma_tf32(acc[1][nf], a[1], b0, b1);
            }
        }
    }

#pragma unroll
    for (int mf = 0; mf < 2; mf++) {
        int r = bm0 + wm + mf * 16 + q4;
#pragma unroll
        for (int nf = 0; nf < 8; nf++) {
            int cidx = bn0 + wn + nf * 8 + 2 * l4;
            float v0 = acc[mf][nf][0], v1 = acc[mf][nf][1];
            float v2 = acc[mf][nf][2], v3 = acc[mf][nf][3];
            if (RND) {
                v0 = to_tf32(v0); v1 = to_tf32(v1);
                v2 = to_tf32(v2); v3 = to_tf32(v3);
            }
            float2 lo = {v0, v1};
            float2 hi = {v2, v3};
            *(float2*)(C + (size_t)r * N + cidx)       = lo;
            *(float2*)(C + (size_t)(r + 8) * N + cidx) = hi;
        }
    }
}

// ---------------------------------------------------------------------------
// Tensor-core flash attention v5.1 (R10 structure + guard removal):
//  - 256 threads (8 warps), 16 queries/warp, 128 queries/CTA.
//  - cp.async double-buffered K/V; pre-rounded tf32 inputs.
//  - ATT_SCALE folded into Q; bitpacked mask, all-ones fast path.
//  - exp(-inf)=0 hardware semantics replace explicit -inf guards
//    (bit-identical for non-fully-masked rows).
// Grid: (SEQN/128, NHEADS, BATCH).
// ---------------------------------------------------------------------------
__global__ __launch_bounds__(256, 2) void attn_tc(const float* __restrict__ Qm,
                                                  const float* __restrict__ KVm,
                                                  const uint32_t* __restrict__ bmask,
                                                  float* __restrict__ Om)
{
    extern __shared__ __align__(16) float smem[];
    float* Ks = smem;                         // 2 x 64 x KS_LD
    float* Vs = smem + 2 * 64 * KS_LD;        // 2 x 64 x VS_LD

    const int tid  = threadIdx.x;
    const int warp = tid >> 5;
    const int lane = tid & 31;
    const int q4   = lane >> 2;
    const int l4   = lane & 3;
    const int n0   = blockIdx.x * 128;
    const int h    = blockIdx.y;
    const int b    = blockIdx.z;
    const int r0   = warp * 16;

    const float* Qbase  = Qm  + ((size_t)b * SEQN) * DIMC       + h * HD;
    const float* KVbase = KVm + ((size_t)b * SEQM) * (2 * DIMC) + h * HD;

    // ---- stage Q (pre-rounded tf32) into Ks region ----
#pragma unroll
    for (int e = 0; e < 8; e++) {
        int i4 = tid + e * 256;
        int i  = i4 >> 4;
        int c4 = (i4 & 15) << 2;
        float4 v = *(const float4*)(Qbase + (size_t)(n0 + i) * DIMC + c4);
        *(float4*)&Ks[i * KS_LD + c4] = v;
    }
    __syncthreads();

    // ---- build Q A-fragments with ATT_SCALE folded in (exact x2^-3) ----
    unsigned qa[8][4];
#pragma unroll
    for (int kt = 0; kt < 8; kt++) {
        int r = r0 + q4;
        qa[kt][0] = __float_as_uint(ATT_SCALE * Ks[(r    ) * KS_LD + kt * 8 + l4    ]);
        qa[kt][1] = __float_as_uint(ATT_SCALE * Ks[(r + 8) * KS_LD + kt * 8 + l4    ]);
        qa[kt][2] = __float_as_uint(ATT_SCALE * Ks[(r    ) * KS_LD + kt * 8 + l4 + 4]);
        qa[kt][3] = __float_as_uint(ATT_SCALE * Ks[(r + 8) * KS_LD + kt * 8 + l4 + 4]);
    }
    __syncthreads();

    // ---- issue tile 0 K/V loads ----
#pragma unroll
    for (int e = 0; e < 4; e++) {
        int i4 = tid + e * 256;
        int j  = i4 >> 4;
        int d4 = (i4 & 15) << 2;
        const float* row = KVbase + (size_t)j * (2 * DIMC) + d4;
        cp_async16(smem_u32(&Ks[j * KS_LD + d4]), row);
        cp_async16(smem_u32(&Vs[j * VS_LD + d4]), row + DIMC);
    }
    cp_commit();

    float oc[8][4];
#pragma unroll
    for (int nt = 0; nt < 8; nt++)
#pragma unroll
        for (int c = 0; c < 4; c++) oc[nt][c] = 0.0f;
    float mrun_lo = -CUDART_INF_F, mrun_hi = -CUDART_INF_F;
    float lsum_lo = 0.0f, lsum_hi = 0.0f;

    const int i0 = n0 + r0 + q4;
    const int i1 = i0 + 8;
    const uint32_t* mp0 = bmask + ((size_t)(b * SEQN + i0) * (SEQM / 32));
    const uint32_t* mp1 = bmask + ((size_t)(b * SEQN + i1) * (SEQM / 32));

    const int T = SEQM / 64;
    for (int t = 0; t < T; t++) {
        const int cur = t & 1;
        if (t + 1 < T) {
            const int nxt = (t + 1) & 1;
            const float* base = KVbase + (size_t)((t + 1) * 64) * (2 * DIMC);
            float* kb = Ks + nxt * 64 * KS_LD;
            float* vb = Vs + nxt * 64 * VS_LD;
#pragma unroll
            for (int e = 0; e < 4; e++) {
                int i4 = tid + e * 256;
                int j  = i4 >> 4;
                int d4 = (i4 & 15) << 2;
                const float* row = base + (size_t)j * (2 * DIMC) + d4;
                cp_async16(smem_u32(&kb[j * KS_LD + d4]), row);
                cp_async16(smem_u32(&vb[j * VS_LD + d4]), row + DIMC);
            }
            cp_commit();
            cp_wait<1>();
        } else {
            cp_commit();
            cp_wait<0>();
        }
        __syncthreads();

        const float* kb = Ks + cur * 64 * KS_LD;
        const float* vb = Vs + cur * 64 * VS_LD;

        // ---- prefetch bitmask words (overlap QK MMAs) ----
        uint2 mw0 = *(const uint2*)(mp0 + t * 2);
        uint2 mw1 = *(const uint2*)(mp1 + t * 2);

        // ---- S = (Q*scale) K^T ----
        float sc[8][4];
#pragma unroll
        for (int nt = 0; nt < 8; nt++)
#pragma unroll
            for (int c = 0; c < 4; c++) sc[nt][c] = 0.0f;
#pragma unroll
        for (int kt = 0; kt < 8; kt++) {
#pragma unroll
            for (int nt = 0; nt < 8; nt++) {
                int jrow = nt * 8 + q4;
                unsigned b0 = __float_as_uint(kb[jrow * KS_LD + kt * 8 + l4    ]);
                unsigned b1 = __float_as_uint(kb[jrow * KS_LD + kt * 8 + l4 + 4]);
                mma_tf32(sc[nt], qa[kt], b0, b1);
            }
        }

        // ---- mask (all-ones fast path; bit test otherwise) ----
        if ((mw0.x & mw0.y & mw1.x & mw1.y) != 0xffffffffu) {
#pragma unroll
            for (int nt = 0; nt < 8; nt++) {
                uint32_t wlo = (nt < 4) ? mw0.x : mw0.y;
                uint32_t whi = (nt < 4) ? mw1.x : mw1.y;
                int bit = (nt * 8 + 2 * l4) & 31;
                if (!((wlo >> bit) & 1u))       sc[nt][0] = -CUDART_INF_F;
                if (!((wlo >> (bit + 1)) & 1u)) sc[nt][1] = -CUDART_INF_F;
                if (!((whi >> bit) & 1u))       sc[nt][2] = -CUDART_INF_F;
                if (!((whi >> (bit + 1)) & 1u)) sc[nt][3] = -CUDART_INF_F;
            }
        }

        // ---- online softmax (exp(-inf)=0 handles masked entries) ----
        float tml = -CUDART_INF_F, tmh = -CUDART_INF_F;
#pragma unroll
        for (int nt = 0; nt < 8; nt++) {
            tml = fmaxf(tml, fmaxf(sc[nt][0], sc[nt][1]));
            tmh = fmaxf(tmh, fmaxf(sc[nt][2], sc[nt][3]));
        }
        tml = fmaxf(tml, __shfl_xor_sync(0xffffffffu, tml, 1));
        tml = fmaxf(tml, __shfl_xor_sync(0xffffffffu, tml, 2));
        tmh = fmaxf(tmh, __shfl_xor_sync(0xffffffffu, tmh, 1));
        tmh = fmaxf(tmh, __shfl_xor_sync(0xffffffffu, tmh, 2));

        float mnew_lo = fmaxf(mrun_lo, tml);
        float mnew_hi = fmaxf(mrun_hi, tmh);

        float ssl = 0.0f, ssh = 0.0f;
#pragma unroll
        for (int nt = 0; nt < 8; nt++) {
            float p0 = __expf(sc[nt][0] - mnew_lo);
            float p1 = __expf(sc[nt][1] - mnew_lo);
            float p2 = __expf(sc[nt][2] - mnew_hi);
            float p3 = __expf(sc[nt][3] - mnew_hi);
            sc[nt][0] = p0; sc[nt][1] = p1; sc[nt][2] = p2; sc[nt][3] = p3;
            ssl += p0 + p1;
            ssh += p2 + p3;
        }
        ssl += __shfl_xor_sync(0xffffffffu, ssl, 1);
        ssl += __shfl_xor_sync(0xffffffffu, ssl, 2);
        ssh += __shfl_xor_sync(0xffffffffu, ssh, 1);
        ssh += __shfl_xor_sync(0xffffffffu, ssh, 2);

        float alpha_lo = __expf(mrun_lo - mnew_lo);   // first tile: exp(-inf)=0
        float alpha_hi = __expf(mrun_hi - mnew_hi);
        lsum_lo = lsum_lo * alpha_lo + ssl;
        lsum_hi = lsum_hi * alpha_hi + ssh;
        mrun_lo = mnew_lo;
        mrun_hi = mnew_hi;
#pragma unroll
        for (int nt = 0; nt < 8; nt++) {
            oc[nt][0] *= alpha_lo; oc[nt][1] *= alpha_lo;
            oc[nt][2] *= alpha_hi; oc[nt][3] *= alpha_hi;
        }

        // ---- O += P @ V ----
        const int base2 = lane & ~3;
        const int src  = base2 | (l4 >> 1);
        const int src2 = src + 2;
        const bool odd = lane & 1;
#pragma unroll
        for (int kt = 0; kt < 8; kt++) {
            float c0 = sc[kt][0], c1 = sc[kt][1], c2 = sc[kt][2], c3 = sc[kt][3];
            float t00 = __shfl_sync(0xffffffffu, c0, src);
            float t01 = __shfl_sync(0xffffffffu, c1, src);
            float t10 = __shfl_sync(0xffffffffu, c2, src);
            float t11 = __shfl_sync(0xffffffffu, c3, src);
            float t20 = __shfl_sync(0xffffffffu, c0, src2);
            float t21 = __shfl_sync(0xffffffffu, c1, src2);
            float t30 = __shfl_sync(0xffffffffu, c2, src2);
            float t31 = __shfl_sync(0xffffffffu, c3, src2);
            unsigned pa[4];
            pa[0] = tf32_bits(odd ? t01 : t00);
            pa[1] = tf32_bits(odd ? t11 : t10);
            pa[2] = tf32_bits(odd ? t21 : t20);
            pa[3] = tf32_bits(odd ? t31 : t30);
#pragma unroll
            for (int nt = 0; nt < 8; nt++) {
                int vrow = kt * 8 + l4;
                unsigned b0 = __float_as_uint(vb[(vrow    ) * VS_LD + nt * 8 + q4]);
                unsigned b1 = __float_as_uint(vb[(vrow + 4) * VS_LD + nt * 8 + q4]);
                mma_tf32(oc[nt], pa, b0, b1);
            }
        }
        __syncthreads();
    }

    // ---- normalize + write O ----
    float inv_lo = 1.0f / lsum_lo;
    float inv_hi = 1.0f / lsum_hi;
    float* orow0 = Om + (size_t)(b * SEQN + i0) * DIMC + h * HD;
    float* orow1 = Om + (size_t)(b * SEQN + i1) * DIMC + h * HD;
#pragma unroll
    for (int nt = 0; nt < 8; nt++) {
        int d0 = nt * 8 + 2 * l4;
        float2 lo = {oc[nt][0] * inv_lo, oc[nt][1] * inv_lo};
        float2 hi = {oc[nt][2] * inv_hi, oc[nt][3] * inv_hi};
        *(float2*)(orow0 + d0) = lo;
        *(float2*)(orow1 + d0) = hi;
    }
}

// ---------------------------------------------------------------------------
extern "C" void kernel_launch(void* const* d_in, const int* in_sizes, int n_in,
                              void* d_out, int out_size)
{
    const float* x    = (const float*)d_in[0];
    const float* ctx  = (const float*)d_in[1];
    const int*   mask = (const int*)d_in[2];
    const float* Wq   = (const float*)d_in[3];
    const float* Wkv  = (const float*)d_in[4];
    const float* Wo   = (const float*)d_in[5];
    float*       out  = (float*)d_out;

    float *gQ, *gKV, *gO;
    uint32_t* gM;
    cudaGetSymbolAddress((void**)&gQ,  g_Q);
    cudaGetSymbolAddress((void**)&gKV, g_KV);
    cudaGetSymbolAddress((void**)&gO,  g_O);
    cudaGetSymbolAddress((void**)&gM,  g_mask);

    cudaFuncSetAttribute(attn_tc, cudaFuncAttributeMaxDynamicSharedMemorySize,
                         ATTN_SMEM_BYTES);
    cudaFuncSetAttribute(tgemm128<true>, cudaFuncAttributeMaxDynamicSharedMemorySize,
                         TG_SMEM_BYTES);
    cudaFuncSetAttribute(tgemm128<false>, cudaFuncAttributeMaxDynamicSharedMemorySize,
                         TG_SMEM_BYTES);

    const int Mrows = BATCH * SEQN;   // 8192
    const int mask_n = BATCH * SEQN * SEQM;

    pack_mask<<<mask_n / 256, 256>>>(mask, gM, mask_n);
    tgemm128<true><<<dim3(DIMC / 128, Mrows / 128), 256, TG_SMEM_BYTES>>>(x, Wq, gQ, Mrows, DIMC, DIMC);
    tgemm128<true><<<dim3(2 * DIMC / 128, Mrows / 128), 256, TG_SMEM_BYTES>>>(ctx, Wkv, gKV, Mrows, 2 * DIMC, DIMC);
    attn_tc<<<dim3(SEQN / 128, NHEADS, BATCH), 256, ATTN_SMEM_BYTES>>>(gQ, gKV, gM, gO);
    tgemm128<false><<<dim3(DIMC / 128, Mrows / 128), 256, TG_SMEM_BYTES>>>(gO, Wo, out, Mrows, DIMC, DIMC);
}